// round 1
// baseline (speedup 1.0000x reference)
#include <cuda_runtime.h>
#include <math.h>

// ---------------------------------------------------------------------------
// Problem constants (fixed by the dataset)
// ---------------------------------------------------------------------------
#define NMAX   16000
#define EMAX   256000
#define ETMAX  (EMAX + NMAX)     // edges + self loops
#define HEADS  4
#define MAXHC  512               // max H*C per layer (layer 1)
#define NGRAPH 64

// ---------------------------------------------------------------------------
// Static device scratch (no allocation allowed)
// ---------------------------------------------------------------------------
__device__ float g_xl   [NMAX * MAXHC];
__device__ float g_xr   [NMAX * MAXHC];
__device__ float g_act0 [NMAX * MAXHC];
__device__ float g_act1 [NMAX * MAXHC];
__device__ float g_logit[ETMAX * HEADS];
__device__ float g_pbuf [ETMAX * HEADS];
__device__ float g_m    [NMAX * HEADS];
__device__ float g_z    [NMAX * HEADS];
__device__ float g_sum  [MAXHC];
__device__ float g_sumsq[MAXHC];
__device__ float g_colA [MAXHC];
__device__ float g_colS [MAXHC];
__device__ float g_hidden[NMAX * 128];
__device__ float g_gate [NMAX];
__device__ float g_pg   [NMAX];
__device__ float g_mb   [NGRAPH];
__device__ float g_zb   [NGRAPH];

// ---------------------------------------------------------------------------
// Helpers
// ---------------------------------------------------------------------------
__device__ __forceinline__ void atomicMaxFloat(float* addr, float val) {
    int old = __float_as_int(*addr);
    while (__int_as_float(old) < val) {
        int assumed = old;
        old = atomicCAS((int*)addr, assumed, __float_as_int(val));
        if (old == assumed) break;
    }
}

__global__ void fill_kernel(float* __restrict__ p, float v, int n) {
    int i = blockIdx.x * blockDim.x + threadIdx.x;
    if (i < n) p[i] = v;
}

__global__ void fill_bias_kernel(float* __restrict__ out, const float* __restrict__ bias,
                                 int total, int Cn) {
    int i = blockIdx.x * blockDim.x + threadIdx.x;
    if (i < total) out[i] = bias[i % Cn];
}

// ---------------------------------------------------------------------------
// Tiled fp32 GEMM: out[M,Nc] = X[M,K] @ W[K,Nc] (+bias) (optional relu)
// Block tile 64x64, K-tile 16, 256 threads, 4x4 per thread.
// ---------------------------------------------------------------------------
#define TM 64
#define TN 64
#define TK 16
__global__ void __launch_bounds__(256)
gemm_kernel(const float* __restrict__ X, const float* __restrict__ W,
            const float* __restrict__ bias, float* __restrict__ out,
            int M, int K, int Nc, int doRelu) {
    __shared__ float As[TK][TM];
    __shared__ float Bs[TK][TN];

    int bm = blockIdx.y * TM;
    int bn = blockIdx.x * TN;
    int tid = threadIdx.x;
    int tx = tid & 15;       // col group
    int ty = tid >> 4;       // row group

    float acc[4][4];
    #pragma unroll
    for (int i = 0; i < 4; i++)
        #pragma unroll
        for (int j = 0; j < 4; j++) acc[i][j] = 0.f;

    // A-tile loader coords: one float4 per thread
    int ar = tid >> 2;            // 0..63 row within tile
    int ac = (tid & 3) << 2;      // 0,4,8,12 col within k-tile

    for (int k0 = 0; k0 < K; k0 += TK) {
        // load A tile (coalesced float4, transpose into As[k][m])
        {
            float4 av = make_float4(0.f, 0.f, 0.f, 0.f);
            int gm = bm + ar;
            if (gm < M && (k0 + ac + 3) < K)
                av = *(const float4*)(X + (size_t)gm * K + k0 + ac);
            As[ac + 0][ar] = av.x;
            As[ac + 1][ar] = av.y;
            As[ac + 2][ar] = av.z;
            As[ac + 3][ar] = av.w;
        }
        // load B tile (row-major, coalesced)
        #pragma unroll
        for (int i = tid; i < TK * TN; i += 256) {
            int n  = i & 63;
            int kk = i >> 6;
            int gn = bn + n;
            int gk = k0 + kk;
            Bs[kk][n] = (gn < Nc && gk < K) ? W[(size_t)gk * Nc + gn] : 0.f;
        }
        __syncthreads();

        #pragma unroll
        for (int kk = 0; kk < TK; kk++) {
            float4 a4 = *(const float4*)&As[kk][ty * 4];
            float4 b4 = *(const float4*)&Bs[kk][tx * 4];
            float a[4] = {a4.x, a4.y, a4.z, a4.w};
            float b[4] = {b4.x, b4.y, b4.z, b4.w};
            #pragma unroll
            for (int i = 0; i < 4; i++)
                #pragma unroll
                for (int j = 0; j < 4; j++)
                    acc[i][j] += a[i] * b[j];
        }
        __syncthreads();
    }

    #pragma unroll
    for (int i = 0; i < 4; i++) {
        int gm = bm + ty * 4 + i;
        if (gm >= M) continue;
        #pragma unroll
        for (int j = 0; j < 4; j++) {
            int gn = bn + tx * 4 + j;
            if (gn < Nc) {
                float v = acc[i][j];
                if (bias) v += bias[gn];
                if (doRelu) v = fmaxf(v, 0.f);
                out[(size_t)gm * Nc + gn] = v;
            }
        }
    }
}

// ---------------------------------------------------------------------------
// GATv2 edge kernels. Warp per (edge, head). Edges e<E use edge_index,
// e>=E are self loops (src=dst=e-E).
// ---------------------------------------------------------------------------
__global__ void edge_logit_kernel(const float* __restrict__ xl, const float* __restrict__ xr,
                                  const int* __restrict__ src, const int* __restrict__ dst,
                                  const float* __restrict__ att,
                                  float* __restrict__ logit, float* __restrict__ m,
                                  int E, int Nn, int C) {
    int gw   = (blockIdx.x * blockDim.x + threadIdx.x) >> 5;
    int lane = threadIdx.x & 31;
    int Et   = E + Nn;
    if (gw >= Et * HEADS) return;
    int e = gw >> 2;          // /HEADS (HEADS==4)
    int h = gw & 3;
    int s = (e < E) ? src[e] : (e - E);
    int d = (e < E) ? dst[e] : (e - E);
    const float* pl = xl + ((size_t)s * HEADS + h) * C;
    const float* pr = xr + ((size_t)d * HEADS + h) * C;
    const float* pa = att + h * C;
    float acc = 0.f;
    for (int c = lane; c < C; c += 32) {
        float v = pl[c] + pr[c];
        v = (v > 0.f) ? v : 0.2f * v;   // leaky relu 0.2
        acc += pa[c] * v;
    }
    #pragma unroll
    for (int o = 16; o > 0; o >>= 1) acc += __shfl_down_sync(0xffffffffu, acc, o);
    if (lane == 0) {
        logit[gw] = acc;
        atomicMaxFloat(&m[d * HEADS + h], acc);
    }
}

__global__ void edge_p_kernel(const int* __restrict__ dst,
                              const float* __restrict__ logit, const float* __restrict__ m,
                              float* __restrict__ p, float* __restrict__ z,
                              int E, int Nn) {
    int idx = blockIdx.x * blockDim.x + threadIdx.x;
    int Et  = E + Nn;
    if (idx >= Et * HEADS) return;
    int e = idx >> 2;
    int h = idx & 3;
    int d = (e < E) ? dst[e] : (e - E);
    float mm = m[d * HEADS + h];
    if (mm < -1e29f) mm = 0.f;   // nan_to_num(neginf=0)
    float pv = expf(logit[idx] - mm);
    p[idx] = pv;
    atomicAdd(&z[d * HEADS + h], pv);
}

__global__ void edge_agg_kernel(const float* __restrict__ xl,
                                const int* __restrict__ src, const int* __restrict__ dst,
                                const float* __restrict__ p, const float* __restrict__ z,
                                float* __restrict__ out, int E, int Nn, int C) {
    int gw   = (blockIdx.x * blockDim.x + threadIdx.x) >> 5;
    int lane = threadIdx.x & 31;
    int Et   = E + Nn;
    if (gw >= Et * HEADS) return;
    int e = gw >> 2;
    int h = gw & 3;
    int s = (e < E) ? src[e] : (e - E);
    int d = (e < E) ? dst[e] : (e - E);
    float alpha = p[gw] / (z[d * HEADS + h] + 1e-16f);
    const float* pl = xl  + ((size_t)s * HEADS + h) * C;
    float*       po = out + ((size_t)d * HEADS + h) * C;
    for (int c = lane; c < C; c += 32)
        atomicAdd(&po[c], alpha * pl[c]);
}

// ---------------------------------------------------------------------------
// GraphNorm (single-graph): column sums/sumsq -> scale/shift -> apply+relu
// ---------------------------------------------------------------------------
__global__ void colstats_kernel(const float* __restrict__ x,
                                float* __restrict__ sum, float* __restrict__ sumsq,
                                int Nn, int Cn) {
    int r0   = blockIdx.x * 64;
    int rend = min(r0 + 64, Nn);
    float s[2] = {0.f, 0.f}, q[2] = {0.f, 0.f};
    for (int r = r0; r < rend; r++) {
        const float* row = x + (size_t)r * Cn;
        int k = 0;
        for (int c = threadIdx.x; c < Cn; c += 256, k++) {
            float v = row[c];
            s[k] += v;
            q[k] += v * v;
        }
    }
    int k = 0;
    for (int c = threadIdx.x; c < Cn; c += 256, k++) {
        atomicAdd(&sum[c],   s[k]);
        atomicAdd(&sumsq[c], q[k]);
    }
}

__global__ void colscale_kernel(const float* __restrict__ sum, const float* __restrict__ sumsq,
                                const float* __restrict__ gw, const float* __restrict__ gb,
                                const float* __restrict__ gm,
                                float* __restrict__ colA, float* __restrict__ colS,
                                int Nn, int Cn) {
    int c = blockIdx.x * blockDim.x + threadIdx.x;
    if (c >= Cn) return;
    float invN = 1.0f / (float)Nn;
    float mean = sum[c] * invN;
    float ms   = gm[c];
    float var  = sumsq[c] * invN - mean * mean * (2.f * ms - ms * ms);
    var = fmaxf(var, 0.f);
    float a = gw[c] * rsqrtf(var + 1e-5f);
    colA[c] = a;
    colS[c] = gb[c] - a * ms * mean;
}

__global__ void norm_relu_kernel(float* __restrict__ x,
                                 const float* __restrict__ colA, const float* __restrict__ colS,
                                 int total, int Cn) {
    int i = blockIdx.x * blockDim.x + threadIdx.x;
    if (i >= total) return;
    int c = i % Cn;
    float v = colA[c] * x[i] + colS[c];
    x[i] = fmaxf(v, 0.f);
}

// ---------------------------------------------------------------------------
// Pooling: gate MLP second matvec, batch softmax, weighted scatter-sum
// ---------------------------------------------------------------------------
__global__ void gate_kernel(const float* __restrict__ hidden, const float* __restrict__ aW2,
                            const float* __restrict__ ab2, float* __restrict__ gate, int Nn) {
    int gw   = (blockIdx.x * blockDim.x + threadIdx.x) >> 5;
    int lane = threadIdx.x & 31;
    if (gw >= Nn) return;
    const float* hr = hidden + (size_t)gw * 128;
    float acc = 0.f;
    for (int c = lane; c < 128; c += 32) acc += hr[c] * aW2[c];
    #pragma unroll
    for (int o = 16; o > 0; o >>= 1) acc += __shfl_down_sync(0xffffffffu, acc, o);
    if (lane == 0) gate[gw] = acc + ab2[0];
}

__global__ void batch_max_kernel(const int* __restrict__ batch, const float* __restrict__ gate,
                                 float* __restrict__ mb, int Nn) {
    int n = blockIdx.x * blockDim.x + threadIdx.x;
    if (n >= Nn) return;
    atomicMaxFloat(&mb[batch[n]], gate[n]);
}

__global__ void batch_p_kernel(const int* __restrict__ batch, const float* __restrict__ gate,
                               const float* __restrict__ mb, float* __restrict__ pg,
                               float* __restrict__ zb, int Nn) {
    int n = blockIdx.x * blockDim.x + threadIdx.x;
    if (n >= Nn) return;
    int b = batch[n];
    float mm = mb[b];
    if (mm < -1e29f) mm = 0.f;
    float pv = expf(gate[n] - mm);
    pg[n] = pv;
    atomicAdd(&zb[b], pv);
}

__global__ void pool_agg_kernel(const int* __restrict__ batch, const float* __restrict__ pg,
                                const float* __restrict__ zb, const float* __restrict__ x,
                                float* __restrict__ out, int Nn) {
    int gw   = (blockIdx.x * blockDim.x + threadIdx.x) >> 5;
    int lane = threadIdx.x & 31;
    if (gw >= Nn) return;
    int b = batch[gw];
    float a = pg[gw] / (zb[b] + 1e-16f);
    const float* xr = x + (size_t)gw * 128;
    for (int c = lane; c < 128; c += 32)
        atomicAdd(&out[b * 128 + c], a * xr[c]);
}

// ---------------------------------------------------------------------------
// Host orchestration
// ---------------------------------------------------------------------------
extern "C" void kernel_launch(void* const* d_in, const int* in_sizes, int n_in,
                              void* d_out, int out_size) {
    const float* x0    = (const float*)d_in[0];
    const int*   ei    = (const int*)d_in[1];
    const int*   batch = (const int*)d_in[2];

    int N = in_sizes[0] / 960;
    int E = in_sizes[1] / 2;
    const int* src = ei;
    const int* dst = ei + E;
    int Et = E + N;

    float *p_xl, *p_xr, *p_a0, *p_a1, *p_logit, *p_p, *p_m, *p_z;
    float *p_sum, *p_sumsq, *p_colA, *p_colS, *p_hidden, *p_gate, *p_pg, *p_mb, *p_zb;
    cudaGetSymbolAddress((void**)&p_xl,    g_xl);
    cudaGetSymbolAddress((void**)&p_xr,    g_xr);
    cudaGetSymbolAddress((void**)&p_a0,    g_act0);
    cudaGetSymbolAddress((void**)&p_a1,    g_act1);
    cudaGetSymbolAddress((void**)&p_logit, g_logit);
    cudaGetSymbolAddress((void**)&p_p,     g_pbuf);
    cudaGetSymbolAddress((void**)&p_m,     g_m);
    cudaGetSymbolAddress((void**)&p_z,     g_z);
    cudaGetSymbolAddress((void**)&p_sum,   g_sum);
    cudaGetSymbolAddress((void**)&p_sumsq, g_sumsq);
    cudaGetSymbolAddress((void**)&p_colA,  g_colA);
    cudaGetSymbolAddress((void**)&p_colS,  g_colS);
    cudaGetSymbolAddress((void**)&p_hidden,g_hidden);
    cudaGetSymbolAddress((void**)&p_gate,  g_gate);
    cudaGetSymbolAddress((void**)&p_pg,    g_pg);
    cudaGetSymbolAddress((void**)&p_mb,    g_mb);
    cudaGetSymbolAddress((void**)&p_zb,    g_zb);

    const int din[3] = {960, 512, 256};
    const int Cc[3]  = {128, 64, 32};

    const float* xin = x0;
    float* acts[2] = {p_a0, p_a1};

    int edgeWarpThreads = Et * HEADS * 32;
    int edgeThreads     = Et * HEADS;

    for (int l = 0; l < 3; l++) {
        int K  = din[l];
        int C  = Cc[l];
        int HC = HEADS * C;
        const float* Wl  = (const float*)d_in[3 + 7 * l];
        const float* Wr  = (const float*)d_in[4 + 7 * l];
        const float* att = (const float*)d_in[5 + 7 * l];
        const float* bb  = (const float*)d_in[6 + 7 * l];
        const float* gw  = (const float*)d_in[7 + 7 * l];
        const float* gb  = (const float*)d_in[8 + 7 * l];
        const float* gm  = (const float*)d_in[9 + 7 * l];
        float* out = acts[l & 1];

        dim3 gblk((HC + TN - 1) / TN, (N + TM - 1) / TM);
        gemm_kernel<<<gblk, 256>>>(xin, Wl, nullptr, p_xl, N, K, HC, 0);
        gemm_kernel<<<gblk, 256>>>(xin, Wr, nullptr, p_xr, N, K, HC, 0);

        fill_kernel<<<(N * HEADS + 255) / 256, 256>>>(p_m, -1e30f, N * HEADS);
        edge_logit_kernel<<<(edgeWarpThreads + 255) / 256, 256>>>(
            p_xl, p_xr, src, dst, att, p_logit, p_m, E, N, C);

        fill_kernel<<<(N * HEADS + 255) / 256, 256>>>(p_z, 0.f, N * HEADS);
        edge_p_kernel<<<(edgeThreads + 255) / 256, 256>>>(
            dst, p_logit, p_m, p_p, p_z, E, N);

        fill_bias_kernel<<<(N * HC + 255) / 256, 256>>>(out, bb, N * HC, HC);
        edge_agg_kernel<<<(edgeWarpThreads + 255) / 256, 256>>>(
            p_xl, src, dst, p_p, p_z, out, E, N, C);

        fill_kernel<<<(HC + 255) / 256, 256>>>(p_sum,   0.f, HC);
        fill_kernel<<<(HC + 255) / 256, 256>>>(p_sumsq, 0.f, HC);
        colstats_kernel<<<(N + 63) / 64, 256>>>(out, p_sum, p_sumsq, N, HC);
        colscale_kernel<<<(HC + 255) / 256, 256>>>(p_sum, p_sumsq, gw, gb, gm,
                                                   p_colA, p_colS, N, HC);
        norm_relu_kernel<<<(N * HC + 255) / 256, 256>>>(out, p_colA, p_colS, N * HC, HC);

        xin = out;
    }

    // Pooling
    const float* aW1 = (const float*)d_in[24];
    const float* ab1 = (const float*)d_in[25];
    const float* aW2 = (const float*)d_in[26];
    const float* ab2 = (const float*)d_in[27];

    dim3 hblk((128 + TN - 1) / TN, (N + TM - 1) / TM);
    gemm_kernel<<<hblk, 256>>>(xin, aW1, ab1, p_hidden, N, 128, 128, 1);
    gate_kernel<<<(N * 32 + 255) / 256, 256>>>(p_hidden, aW2, ab2, p_gate, N);

    fill_kernel<<<1, NGRAPH>>>(p_mb, -1e30f, NGRAPH);
    batch_max_kernel<<<(N + 255) / 256, 256>>>(batch, p_gate, p_mb, N);
    fill_kernel<<<1, NGRAPH>>>(p_zb, 0.f, NGRAPH);
    batch_p_kernel<<<(N + 255) / 256, 256>>>(batch, p_gate, p_mb, p_pg, p_zb, N);

    fill_kernel<<<(NGRAPH * 128 + 255) / 256, 256>>>((float*)d_out, 0.f, NGRAPH * 128);
    pool_agg_kernel<<<(N * 32 + 255) / 256, 256>>>(batch, p_pg, p_zb, xin,
                                                   (float*)d_out, N);
}

// round 2
// speedup vs baseline: 1.5622x; 1.5622x over previous
#include <cuda_runtime.h>
#include <math.h>

// ---------------------------------------------------------------------------
// Problem constants
// ---------------------------------------------------------------------------
#define NMAX   16000
#define EMAX   256000
#define ETMAX  (EMAX + NMAX)
#define HEADS  4
#define MAXHC  512
#define NGRAPH 64

// ---------------------------------------------------------------------------
// Static device scratch
// ---------------------------------------------------------------------------
__device__ float g_xl   [NMAX * MAXHC];
__device__ float g_xr   [NMAX * MAXHC];
__device__ float g_act0 [NMAX * MAXHC];
__device__ float g_act1 [NMAX * MAXHC];
__device__ float g_logit[ETMAX * HEADS];
__device__ float g_alpha[ETMAX * HEADS];
__device__ float g_stats[2 * MAXHC];
__device__ float g_colA [MAXHC];
__device__ float g_colS [MAXHC];
__device__ float g_hidden[NMAX * 128];
__device__ float g_gate [NMAX];
__device__ int   g_deg  [NMAX];
__device__ int   g_ptr  [NMAX + 1];
__device__ int   g_pos  [NMAX];
__device__ int   g_eid  [ETMAX];
__device__ int   g_gs   [NGRAPH];
__device__ int   g_ge   [NGRAPH];

// ---------------------------------------------------------------------------
// Small utility kernels
// ---------------------------------------------------------------------------
__global__ void fill_f_kernel(float* __restrict__ p, float v, int n) {
    int i = blockIdx.x * blockDim.x + threadIdx.x;
    if (i < n) p[i] = v;
}
__global__ void fill_i_kernel(int* __restrict__ p, int v, int n) {
    int i = blockIdx.x * blockDim.x + threadIdx.x;
    if (i < n) p[i] = v;
}

// ---------------------------------------------------------------------------
// CSR build over dst (edges + implicit self loops e>=E with src=dst=e-E)
// ---------------------------------------------------------------------------
__global__ void csr_count_kernel(const int* __restrict__ dst, int* __restrict__ deg,
                                 int E, int Nn) {
    int e = blockIdx.x * blockDim.x + threadIdx.x;
    int Et = E + Nn;
    if (e >= Et) return;
    int d = (e < E) ? dst[e] : (e - E);
    atomicAdd(&deg[d], 1);
}

__global__ void csr_scan_kernel(const int* __restrict__ deg, int* __restrict__ ptr,
                                int* __restrict__ pos, int n) {
    __shared__ int ss[1024];
    int t = threadIdx.x;
    int base = t * 16;
    int loc[16];
    int s = 0;
    #pragma unroll
    for (int i = 0; i < 16; i++) {
        int v = (base + i < n) ? deg[base + i] : 0;
        loc[i] = v; s += v;
    }
    ss[t] = s;
    __syncthreads();
    for (int off = 1; off < 1024; off <<= 1) {
        int v = (t >= off) ? ss[t - off] : 0;
        __syncthreads();
        ss[t] += v;
        __syncthreads();
    }
    int run = (t > 0) ? ss[t - 1] : 0;
    #pragma unroll
    for (int i = 0; i < 16; i++) {
        if (base + i < n) {
            ptr[base + i] = run;
            pos[base + i] = run;
            run += loc[i];
        }
    }
    if (t == 1023) ptr[n] = ss[1023];
}

__global__ void csr_scatter_kernel(const int* __restrict__ dst, int* __restrict__ pos,
                                   int* __restrict__ eid, int E, int Nn) {
    int e = blockIdx.x * blockDim.x + threadIdx.x;
    int Et = E + Nn;
    if (e >= Et) return;
    int d = (e < E) ? dst[e] : (e - E);
    int slot = atomicAdd(&pos[d], 1);
    eid[slot] = e;
}

// ---------------------------------------------------------------------------
// SGEMM: out[M,*] = X[M,K] @ W[K,HC]; optionally dual-weight (Wl|Wr fused):
// grid.x spans 2*HC/128 tiles, first half writes out0 via W0, second out1/W1.
// 128x128x16 tiles, 256 threads, 8x8 per thread (quad layout), double-buffered.
// Assumes: M%128==0, K%16==0, HC%128==0 (true for all shapes here).
// ---------------------------------------------------------------------------
__global__ void __launch_bounds__(256)
sgemm_dual(const float* __restrict__ X,
           const float* __restrict__ W0, const float* __restrict__ W1,
           float* __restrict__ out0, float* __restrict__ out1,
           const float* __restrict__ bias, int relu,
           int M, int K, int HC) {
    __shared__ float As[2][16 * 128];
    __shared__ float Bs[2][16 * 128];

    const int t  = threadIdx.x;
    const int bm = blockIdx.y * 128;
    int bn = blockIdx.x * 128;

    const float* W = W0;
    float* out = out0;
    int col0 = bn;
    if (W1 != nullptr && bn >= HC) { W = W1; out = out1; col0 = bn - HC; }

    // A loader: float4 id f in {t, t+256}: row r=f>>2 (0..127), colquad c4=f&3
    const int arA = t >> 2;
    const int acA = t & 3;
    const float* Aptr0 = X + (size_t)(bm + arA) * K + acA * 4;
    const float* Aptr1 = X + (size_t)(bm + arA + 64) * K + acA * 4;
    // B loader: f in {t, t+256}: kk=f>>5, colquad=f&31
    const int bkB = t >> 5;
    const int bcB = t & 31;
    const float* Bptr0 = W + (size_t)bkB * HC + col0 + bcB * 4;
    const float* Bptr1 = Bptr0 + (size_t)8 * HC;

    const int ty4 = (t >> 4) * 4;
    const int tx4 = (t & 15) * 4;

    float acc[8][8];
    #pragma unroll
    for (int i = 0; i < 8; i++)
        #pragma unroll
        for (int j = 0; j < 8; j++) acc[i][j] = 0.f;

    float4 pa0, pa1, pb0, pb1;

    // prologue: tile 0 -> smem[0]
    pa0 = *(const float4*)(Aptr0);
    pa1 = *(const float4*)(Aptr1);
    pb0 = *(const float4*)(Bptr0);
    pb1 = *(const float4*)(Bptr1);
    {
        float* As_ = As[0];
        float* Bs_ = Bs[0];
        As_[(acA * 4 + 0) * 128 + arA]      = pa0.x;
        As_[(acA * 4 + 1) * 128 + arA]      = pa0.y;
        As_[(acA * 4 + 2) * 128 + arA]      = pa0.z;
        As_[(acA * 4 + 3) * 128 + arA]      = pa0.w;
        As_[(acA * 4 + 0) * 128 + arA + 64] = pa1.x;
        As_[(acA * 4 + 1) * 128 + arA + 64] = pa1.y;
        As_[(acA * 4 + 2) * 128 + arA + 64] = pa1.z;
        As_[(acA * 4 + 3) * 128 + arA + 64] = pa1.w;
        *(float4*)&Bs_[bkB * 128 + bcB * 4]       = pb0;
        *(float4*)&Bs_[(bkB + 8) * 128 + bcB * 4] = pb1;
    }
    __syncthreads();

    const int nt = K >> 4;
    for (int it = 0; it < nt; it++) {
        if (it + 1 < nt) {
            int k0 = (it + 1) << 4;
            pa0 = *(const float4*)(Aptr0 + k0);
            pa1 = *(const float4*)(Aptr1 + k0);
            pb0 = *(const float4*)(Bptr0 + (size_t)k0 * HC);
            pb1 = *(const float4*)(Bptr1 + (size_t)k0 * HC);
        }
        const float* As_ = As[it & 1];
        const float* Bs_ = Bs[it & 1];
        #pragma unroll
        for (int kk = 0; kk < 16; kk++) {
            float4 t0 = *(const float4*)(As_ + kk * 128 + ty4);
            float4 t1 = *(const float4*)(As_ + kk * 128 + ty4 + 64);
            float4 u0 = *(const float4*)(Bs_ + kk * 128 + tx4);
            float4 u1 = *(const float4*)(Bs_ + kk * 128 + tx4 + 64);
            float a[8] = {t0.x, t0.y, t0.z, t0.w, t1.x, t1.y, t1.z, t1.w};
            float b[8] = {u0.x, u0.y, u0.z, u0.w, u1.x, u1.y, u1.z, u1.w};
            #pragma unroll
            for (int i = 0; i < 8; i++)
                #pragma unroll
                for (int j = 0; j < 8; j++)
                    acc[i][j] += a[i] * b[j];
        }
        if (it + 1 < nt) {
            __syncthreads();
            float* Aw = As[(it + 1) & 1];
            float* Bw = Bs[(it + 1) & 1];
            Aw[(acA * 4 + 0) * 128 + arA]      = pa0.x;
            Aw[(acA * 4 + 1) * 128 + arA]      = pa0.y;
            Aw[(acA * 4 + 2) * 128 + arA]      = pa0.z;
            Aw[(acA * 4 + 3) * 128 + arA]      = pa0.w;
            Aw[(acA * 4 + 0) * 128 + arA + 64] = pa1.x;
            Aw[(acA * 4 + 1) * 128 + arA + 64] = pa1.y;
            Aw[(acA * 4 + 2) * 128 + arA + 64] = pa1.z;
            Aw[(acA * 4 + 3) * 128 + arA + 64] = pa1.w;
            *(float4*)&Bw[bkB * 128 + bcB * 4]       = pb0;
            *(float4*)&Bw[(bkB + 8) * 128 + bcB * 4] = pb1;
            __syncthreads();
        }
    }

    // epilogue
    #pragma unroll
    for (int hi = 0; hi < 2; hi++) {
        #pragma unroll
        for (int i = 0; i < 4; i++) {
            int gr = bm + hi * 64 + ty4 + i;
            #pragma unroll
            for (int hj = 0; hj < 2; hj++) {
                int gc = col0 + hj * 64 + tx4;
                float4 v;
                v.x = acc[hi * 4 + i][hj * 4 + 0];
                v.y = acc[hi * 4 + i][hj * 4 + 1];
                v.z = acc[hi * 4 + i][hj * 4 + 2];
                v.w = acc[hi * 4 + i][hj * 4 + 3];
                if (bias) {
                    float4 bv = *(const float4*)(bias + gc);
                    v.x += bv.x; v.y += bv.y; v.z += bv.z; v.w += bv.w;
                }
                if (relu) {
                    v.x = fmaxf(v.x, 0.f); v.y = fmaxf(v.y, 0.f);
                    v.z = fmaxf(v.z, 0.f); v.w = fmaxf(v.w, 0.f);
                }
                *(float4*)&out[(size_t)gr * HC + gc] = v;
            }
        }
    }
}

// ---------------------------------------------------------------------------
// Edge logits. Warp handles (32/C4) heads of one edge; C4 = C/4 lanes per head.
// ---------------------------------------------------------------------------
__global__ void edge_logit_kernel(const float4* __restrict__ xl4, const float4* __restrict__ xr4,
                                  const int* __restrict__ src, const int* __restrict__ dst,
                                  const float4* __restrict__ att4,
                                  float* __restrict__ logit,
                                  int E, int Nn, int C4, int c4shift, int HC4, int WPE) {
    int gw   = (blockIdx.x * blockDim.x + threadIdx.x) >> 5;
    int lane = threadIdx.x & 31;
    int Et   = E + Nn;
    if (gw >= Et * WPE) return;
    int e    = gw / WPE;
    int wsub = gw - e * WPE;
    int hperw = 32 >> c4shift;
    int hloc = lane >> c4shift;
    int h    = wsub * hperw + hloc;
    int j    = lane & (C4 - 1);

    int s, d;
    if (e < E) { s = src[e]; d = dst[e]; } else { s = d = e - E; }

    float4 l = xl4[(size_t)s * HC4 + h * C4 + j];
    float4 r = xr4[(size_t)d * HC4 + h * C4 + j];
    float4 a = att4[h * C4 + j];
    float v, acc = 0.f;
    v = l.x + r.x; v = (v > 0.f) ? v : 0.2f * v; acc += a.x * v;
    v = l.y + r.y; v = (v > 0.f) ? v : 0.2f * v; acc += a.y * v;
    v = l.z + r.z; v = (v > 0.f) ? v : 0.2f * v; acc += a.z * v;
    v = l.w + r.w; v = (v > 0.f) ? v : 0.2f * v; acc += a.w * v;

    for (int off = C4 >> 1; off > 0; off >>= 1)
        acc += __shfl_xor_sync(0xffffffffu, acc, off);
    if (j == 0)
        logit[e * HEADS + h] = acc;
}

// ---------------------------------------------------------------------------
// Per-node softmax over incoming edges (CSR), writes per-edge alpha (4 heads).
// Warp per node.
// ---------------------------------------------------------------------------
__global__ void node_softmax_kernel(const int* __restrict__ ptr, const int* __restrict__ eid,
                                    const float4* __restrict__ logit4,
                                    float4* __restrict__ alpha4, int Nn) {
    int n    = (blockIdx.x * blockDim.x + threadIdx.x) >> 5;
    int lane = threadIdx.x & 31;
    if (n >= Nn) return;
    int beg = ptr[n], end = ptr[n + 1];

    float m0 = -1e30f, m1 = -1e30f, m2 = -1e30f, m3 = -1e30f;
    for (int i = beg + lane; i < end; i += 32) {
        float4 lg = logit4[eid[i]];
        m0 = fmaxf(m0, lg.x); m1 = fmaxf(m1, lg.y);
        m2 = fmaxf(m2, lg.z); m3 = fmaxf(m3, lg.w);
    }
    #pragma unroll
    for (int off = 16; off > 0; off >>= 1) {
        m0 = fmaxf(m0, __shfl_xor_sync(0xffffffffu, m0, off));
        m1 = fmaxf(m1, __shfl_xor_sync(0xffffffffu, m1, off));
        m2 = fmaxf(m2, __shfl_xor_sync(0xffffffffu, m2, off));
        m3 = fmaxf(m3, __shfl_xor_sync(0xffffffffu, m3, off));
    }
    float z0 = 0.f, z1 = 0.f, z2 = 0.f, z3 = 0.f;
    for (int i = beg + lane; i < end; i += 32) {
        float4 lg = logit4[eid[i]];
        z0 += expf(lg.x - m0); z1 += expf(lg.y - m1);
        z2 += expf(lg.z - m2); z3 += expf(lg.w - m3);
    }
    #pragma unroll
    for (int off = 16; off > 0; off >>= 1) {
        z0 += __shfl_xor_sync(0xffffffffu, z0, off);
        z1 += __shfl_xor_sync(0xffffffffu, z1, off);
        z2 += __shfl_xor_sync(0xffffffffu, z2, off);
        z3 += __shfl_xor_sync(0xffffffffu, z3, off);
    }
    float i0 = 1.f / (z0 + 1e-16f), i1 = 1.f / (z1 + 1e-16f);
    float i2 = 1.f / (z2 + 1e-16f), i3 = 1.f / (z3 + 1e-16f);
    for (int i = beg + lane; i < end; i += 32) {
        int e = eid[i];
        float4 lg = logit4[e];
        float4 al;
        al.x = expf(lg.x - m0) * i0;
        al.y = expf(lg.y - m1) * i1;
        al.z = expf(lg.z - m2) * i2;
        al.w = expf(lg.w - m3) * i3;
        alpha4[e] = al;
    }
}

// ---------------------------------------------------------------------------
// Aggregation: warp per node, register accumulation, single coalesced write.
// NV4 = HC/128 float4 regs per lane. head of column-quad j is j >> c4shift.
// ---------------------------------------------------------------------------
template <int NV4>
__global__ void node_agg_kernel(const float4* __restrict__ xl4, const int* __restrict__ src,
                                const int* __restrict__ ptr, const int* __restrict__ eid,
                                const float* __restrict__ alpha,
                                float4* __restrict__ out4,
                                int E, int Nn, int HC4, int c4shift) {
    int n    = (blockIdx.x * blockDim.x + threadIdx.x) >> 5;
    int lane = threadIdx.x & 31;
    if (n >= Nn) return;
    int beg = ptr[n], end = ptr[n + 1];

    float4 acc[NV4];
    #pragma unroll
    for (int r = 0; r < NV4; r++) acc[r] = make_float4(0.f, 0.f, 0.f, 0.f);

    for (int i = beg; i < end; i++) {
        int e = eid[i];
        int s = (e < E) ? src[e] : n;
        const float4* row = xl4 + (size_t)s * HC4;
        #pragma unroll
        for (int r = 0; r < NV4; r++) {
            int j = r * 32 + lane;
            float a = alpha[e * HEADS + (j >> c4shift)];
            float4 x = row[j];
            acc[r].x += a * x.x; acc[r].y += a * x.y;
            acc[r].z += a * x.z; acc[r].w += a * x.w;
        }
    }
    #pragma unroll
    for (int r = 0; r < NV4; r++)
        out4[(size_t)n * HC4 + r * 32 + lane] = acc[r];
}

// ---------------------------------------------------------------------------
// GraphNorm: column stats on raw aggregate; bias folded into affine.
// ---------------------------------------------------------------------------
__global__ void colstats_kernel(const float* __restrict__ x, float* __restrict__ stats,
                                int Nn, int Cn) {
    int r0   = blockIdx.x * 64;
    int rend = min(r0 + 64, Nn);
    float s[2] = {0.f, 0.f}, q[2] = {0.f, 0.f};
    for (int r = r0; r < rend; r++) {
        const float* row = x + (size_t)r * Cn;
        int k = 0;
        for (int c = threadIdx.x; c < Cn; c += 256, k++) {
            float v = row[c];
            s[k] += v; q[k] += v * v;
        }
    }
    int k = 0;
    for (int c = threadIdx.x; c < Cn; c += 256, k++) {
        atomicAdd(&stats[c],      s[k]);
        atomicAdd(&stats[Cn + c], q[k]);
    }
}

__global__ void colscale_kernel(const float* __restrict__ stats,
                                const float* __restrict__ bias,
                                const float* __restrict__ gw, const float* __restrict__ gb,
                                const float* __restrict__ gm,
                                float* __restrict__ colA, float* __restrict__ colS,
                                int Nn, int Cn) {
    int c = blockIdx.x * blockDim.x + threadIdx.x;
    if (c >= Cn) return;
    float invN = 1.0f / (float)Nn;
    float ma = stats[c] * invN;          // mean of aggregate
    float q  = stats[Cn + c] * invN;     // E[agg^2]
    float b  = bias[c];
    float mx = ma + b;                   // mean of x = agg + bias
    float tt = b - gm[c] * mx;           // xc = agg + tt
    float var = q + 2.f * tt * ma + tt * tt;
    var = fmaxf(var, 0.f);
    float A = gw[c] * rsqrtf(var + 1e-5f);
    colA[c] = A;
    colS[c] = A * tt + gb[c];
}

__global__ void norm_relu_kernel(float4* __restrict__ x4,
                                 const float4* __restrict__ colA4,
                                 const float4* __restrict__ colS4,
                                 int total4, int Cn4) {
    int i = blockIdx.x * blockDim.x + threadIdx.x;
    if (i >= total4) return;
    int c = i % Cn4;
    float4 v = x4[i];
    float4 A = colA4[c];
    float4 S = colS4[c];
    v.x = fmaxf(A.x * v.x + S.x, 0.f);
    v.y = fmaxf(A.y * v.y + S.y, 0.f);
    v.z = fmaxf(A.z * v.z + S.z, 0.f);
    v.w = fmaxf(A.w * v.w + S.w, 0.f);
    x4[i] = v;
}

// ---------------------------------------------------------------------------
// Pooling
// ---------------------------------------------------------------------------
__global__ void gate_kernel(const float* __restrict__ hidden, const float* __restrict__ aW2,
                            const float* __restrict__ ab2, float* __restrict__ gate, int Nn) {
    int gw   = (blockIdx.x * blockDim.x + threadIdx.x) >> 5;
    int lane = threadIdx.x & 31;
    if (gw >= Nn) return;
    const float* hr = hidden + (size_t)gw * 128;
    float acc = 0.f;
    #pragma unroll
    for (int c = 0; c < 4; c++) acc += hr[lane + c * 32] * aW2[lane + c * 32];
    #pragma unroll
    for (int o = 16; o > 0; o >>= 1) acc += __shfl_down_sync(0xffffffffu, acc, o);
    if (lane == 0) gate[gw] = acc + ab2[0];
}

__global__ void graph_bounds_kernel(const int* __restrict__ batch,
                                    int* __restrict__ gs, int* __restrict__ ge, int Nn) {
    int n = blockIdx.x * blockDim.x + threadIdx.x;
    if (n >= Nn) return;
    int b = batch[n];
    atomicMin(&gs[b], n);
    atomicMax(&ge[b], n + 1);
}

__global__ void pool_kernel(const float* __restrict__ x, const float* __restrict__ gate,
                            const int* __restrict__ gs, const int* __restrict__ ge,
                            float* __restrict__ out) {
    __shared__ float red[128];
    __shared__ float wbuf[128];
    int b = blockIdx.x;
    int t = threadIdx.x;
    int beg = gs[b], end = ge[b];

    float mx = -1e30f;
    for (int n = beg + t; n < end; n += 128) mx = fmaxf(mx, gate[n]);
    red[t] = mx; __syncthreads();
    for (int o = 64; o > 0; o >>= 1) {
        if (t < o) red[t] = fmaxf(red[t], red[t + o]);
        __syncthreads();
    }
    float m = red[0];
    if (m < -1e29f) m = 0.f;
    __syncthreads();

    float zs = 0.f;
    for (int n = beg + t; n < end; n += 128) zs += expf(gate[n] - m);
    red[t] = zs; __syncthreads();
    for (int o = 64; o > 0; o >>= 1) {
        if (t < o) red[t] += red[t + o];
        __syncthreads();
    }
    float inv = 1.f / (red[0] + 1e-16f);
    __syncthreads();

    float acc = 0.f;
    for (int base = beg; base < end; base += 128) {
        int n = base + t;
        wbuf[t] = (n < end) ? expf(gate[n] - m) * inv : 0.f;
        __syncthreads();
        int cnt = min(128, end - base);
        for (int k = 0; k < cnt; k++)
            acc += wbuf[k] * x[(size_t)(base + k) * 128 + t];
        __syncthreads();
    }
    out[b * 128 + t] = acc;
}

// ---------------------------------------------------------------------------
// Host orchestration
// ---------------------------------------------------------------------------
extern "C" void kernel_launch(void* const* d_in, const int* in_sizes, int n_in,
                              void* d_out, int out_size) {
    const float* x0    = (const float*)d_in[0];
    const int*   ei    = (const int*)d_in[1];
    const int*   batch = (const int*)d_in[2];

    int N = in_sizes[0] / 960;
    int E = in_sizes[1] / 2;
    const int* src = ei;
    const int* dst = ei + E;
    int Et = E + N;

    float *p_xl, *p_xr, *p_a0, *p_a1, *p_logit, *p_alpha, *p_stats, *p_colA, *p_colS;
    float *p_hidden, *p_gate;
    int *p_deg, *p_ptr, *p_pos, *p_eid, *p_gs, *p_ge;
    cudaGetSymbolAddress((void**)&p_xl,    g_xl);
    cudaGetSymbolAddress((void**)&p_xr,    g_xr);
    cudaGetSymbolAddress((void**)&p_a0,    g_act0);
    cudaGetSymbolAddress((void**)&p_a1,    g_act1);
    cudaGetSymbolAddress((void**)&p_logit, g_logit);
    cudaGetSymbolAddress((void**)&p_alpha, g_alpha);
    cudaGetSymbolAddress((void**)&p_stats, g_stats);
    cudaGetSymbolAddress((void**)&p_colA,  g_colA);
    cudaGetSymbolAddress((void**)&p_colS,  g_colS);
    cudaGetSymbolAddress((void**)&p_hidden,g_hidden);
    cudaGetSymbolAddress((void**)&p_gate,  g_gate);
    cudaGetSymbolAddress((void**)&p_deg,   g_deg);
    cudaGetSymbolAddress((void**)&p_ptr,   g_ptr);
    cudaGetSymbolAddress((void**)&p_pos,   g_pos);
    cudaGetSymbolAddress((void**)&p_eid,   g_eid);
    cudaGetSymbolAddress((void**)&p_gs,    g_gs);
    cudaGetSymbolAddress((void**)&p_ge,    g_ge);

    // ---- CSR build (graph is identical across layers) ----
    fill_i_kernel<<<(N + 255) / 256, 256>>>(p_deg, 0, N);
    csr_count_kernel<<<(Et + 255) / 256, 256>>>(dst, p_deg, E, N);
    csr_scan_kernel<<<1, 1024>>>(p_deg, p_ptr, p_pos, N);
    csr_scatter_kernel<<<(Et + 255) / 256, 256>>>(dst, p_pos, p_eid, E, N);

    const int din[3] = {960, 512, 256};
    const int Cc[3]  = {128, 64, 32};

    const float* xin = x0;
    float* acts[2] = {p_a0, p_a1};

    for (int l = 0; l < 3; l++) {
        int K  = din[l];
        int C  = Cc[l];
        int HC = HEADS * C;
        int C4 = C / 4;
        int c4shift = (C == 128) ? 5 : (C == 64 ? 4 : 3);
        int HC4 = HC / 4;
        int WPE = (HEADS * C4) / 32;   // warps per edge in logit kernel
        const float* Wl  = (const float*)d_in[3 + 7 * l];
        const float* Wr  = (const float*)d_in[4 + 7 * l];
        const float* att = (const float*)d_in[5 + 7 * l];
        const float* bb  = (const float*)d_in[6 + 7 * l];
        const float* gw  = (const float*)d_in[7 + 7 * l];
        const float* gb  = (const float*)d_in[8 + 7 * l];
        const float* gm  = (const float*)d_in[9 + 7 * l];
        float* out = acts[l & 1];

        // fused dual GEMM -> xl, xr
        dim3 gblk(2 * HC / 128, N / 128);
        sgemm_dual<<<gblk, 256>>>(xin, Wl, Wr, p_xl, p_xr, nullptr, 0, N, K, HC);

        // edge logits
        int warps = Et * WPE;
        edge_logit_kernel<<<(warps * 32 + 255) / 256, 256>>>(
            (const float4*)p_xl, (const float4*)p_xr, src, dst,
            (const float4*)att, p_logit, E, N, C4, c4shift, HC4, WPE);

        // per-node softmax -> alpha
        node_softmax_kernel<<<(N * 32 + 255) / 256, 256>>>(
            p_ptr, p_eid, (const float4*)p_logit, (float4*)p_alpha, N);

        // aggregation (no atomics, no prefill)
        int aggBlocks = (N * 32 + 255) / 256;
        if (HC4 == 128)
            node_agg_kernel<4><<<aggBlocks, 256>>>((const float4*)p_xl, src, p_ptr, p_eid,
                                                   p_alpha, (float4*)out, E, N, HC4, c4shift);
        else if (HC4 == 64)
            node_agg_kernel<2><<<aggBlocks, 256>>>((const float4*)p_xl, src, p_ptr, p_eid,
                                                   p_alpha, (float4*)out, E, N, HC4, c4shift);
        else
            node_agg_kernel<1><<<aggBlocks, 256>>>((const float4*)p_xl, src, p_ptr, p_eid,
                                                   p_alpha, (float4*)out, E, N, HC4, c4shift);

        // GraphNorm (bias folded) + ReLU
        fill_f_kernel<<<(2 * HC + 255) / 256, 256>>>(p_stats, 0.f, 2 * HC);
        colstats_kernel<<<(N + 63) / 64, 256>>>(out, p_stats, N, HC);
        colscale_kernel<<<(HC + 255) / 256, 256>>>(p_stats, bb, gw, gb, gm,
                                                   p_colA, p_colS, N, HC);
        norm_relu_kernel<<<(N * HC4 + 255) / 256, 256>>>(
            (float4*)out, (const float4*)p_colA, (const float4*)p_colS, N * HC4, HC4);

        xin = out;
    }

    // ---- Pooling ----
    const float* aW1 = (const float*)d_in[24];
    const float* ab1 = (const float*)d_in[25];
    const float* aW2 = (const float*)d_in[26];
    const float* ab2 = (const float*)d_in[27];

    dim3 hblk(1, N / 128);
    sgemm_dual<<<hblk, 256>>>(xin, aW1, nullptr, p_hidden, nullptr, ab1, 1, N, 128, 128);
    gate_kernel<<<(N * 32 + 255) / 256, 256>>>(p_hidden, aW2, ab2, p_gate, N);

    fill_i_kernel<<<1, NGRAPH>>>(p_gs, N, NGRAPH);
    fill_i_kernel<<<1, NGRAPH>>>(p_ge, 0, NGRAPH);
    graph_bounds_kernel<<<(N + 255) / 256, 256>>>(batch, p_gs, p_ge, N);
    pool_kernel<<<NGRAPH, 128>>>(xin, p_gate, p_gs, p_ge, (float*)d_out);
}

// round 3
// speedup vs baseline: 1.7367x; 1.1117x over previous
#include <cuda_runtime.h>
#include <math.h>
#include <stdint.h>

// ---------------------------------------------------------------------------
// Problem constants
// ---------------------------------------------------------------------------
#define NMAX   16000
#define EMAX   256000
#define ETMAX  (EMAX + NMAX)
#define HEADS  4
#define MAXHC  512
#define NGRAPH 64

// ---------------------------------------------------------------------------
// Static device scratch
// ---------------------------------------------------------------------------
__device__ float g_xl   [NMAX * MAXHC];
__device__ float g_xr   [NMAX * MAXHC];
__device__ float g_act0 [NMAX * MAXHC];
__device__ float g_act1 [NMAX * MAXHC];
__device__ float g_logit[ETMAX * HEADS];
__device__ float g_alpha[ETMAX * HEADS];
__device__ float g_stats[2 * MAXHC];
__device__ float g_colA [MAXHC];
__device__ float g_colS [MAXHC];
__device__ float g_hidden[NMAX * 128];
__device__ float g_gate [NMAX];
__device__ int   g_deg  [NMAX];
__device__ int   g_ptr  [NMAX + 1];
__device__ int   g_pos  [NMAX];
__device__ int   g_eid  [ETMAX];
__device__ int   g_gs   [NGRAPH];
__device__ int   g_ge   [NGRAPH];

// ---------------------------------------------------------------------------
// Small utility kernels
// ---------------------------------------------------------------------------
__global__ void fill_f_kernel(float* __restrict__ p, float v, int n) {
    int i = blockIdx.x * blockDim.x + threadIdx.x;
    if (i < n) p[i] = v;
}
__global__ void fill_i_kernel(int* __restrict__ p, int v, int n) {
    int i = blockIdx.x * blockDim.x + threadIdx.x;
    if (i < n) p[i] = v;
}

// ---------------------------------------------------------------------------
// CSR build over dst
// ---------------------------------------------------------------------------
__global__ void csr_count_kernel(const int* __restrict__ dst, int* __restrict__ deg,
                                 int E, int Nn) {
    int e = blockIdx.x * blockDim.x + threadIdx.x;
    int Et = E + Nn;
    if (e >= Et) return;
    int d = (e < E) ? dst[e] : (e - E);
    atomicAdd(&deg[d], 1);
}

__global__ void csr_scan_kernel(const int* __restrict__ deg, int* __restrict__ ptr,
                                int* __restrict__ pos, int n) {
    __shared__ int ss[1024];
    int t = threadIdx.x;
    int base = t * 16;
    int loc[16];
    int s = 0;
    #pragma unroll
    for (int i = 0; i < 16; i++) {
        int v = (base + i < n) ? deg[base + i] : 0;
        loc[i] = v; s += v;
    }
    ss[t] = s;
    __syncthreads();
    for (int off = 1; off < 1024; off <<= 1) {
        int v = (t >= off) ? ss[t - off] : 0;
        __syncthreads();
        ss[t] += v;
        __syncthreads();
    }
    int run = (t > 0) ? ss[t - 1] : 0;
    #pragma unroll
    for (int i = 0; i < 16; i++) {
        if (base + i < n) {
            ptr[base + i] = run;
            pos[base + i] = run;
            run += loc[i];
        }
    }
    if (t == 1023) ptr[n] = ss[1023];
}

__global__ void csr_scatter_kernel(const int* __restrict__ dst, int* __restrict__ pos,
                                   int* __restrict__ eid, int E, int Nn) {
    int e = blockIdx.x * blockDim.x + threadIdx.x;
    int Et = E + Nn;
    if (e >= Et) return;
    int d = (e < E) ? dst[e] : (e - E);
    int slot = atomicAdd(&pos[d], 1);
    eid[slot] = e;
}

// ---------------------------------------------------------------------------
// TF32 tensor-core GEMM with 3xTF32 error compensation.
// out[M,HC] = X[M,K] @ W[K,HC]; dual-weight option as before.
// Block 128x128xK16, 8 warps (2x4), warp tile 64x32, mma m16n8k8.
// Assumes M%128==0, K%16==0, HC%128==0.
// ---------------------------------------------------------------------------
#define GPITCH 132

__device__ __forceinline__ void tf32split(float x, uint32_t& hi, uint32_t& lo) {
    uint32_t h;
    asm("cvt.rna.tf32.f32 %0, %1;" : "=r"(h) : "f"(x));
    float lf = x - __uint_as_float(h);
    uint32_t l;
    asm("cvt.rna.tf32.f32 %0, %1;" : "=r"(l) : "f"(lf));
    hi = h; lo = l;
}

__device__ __forceinline__ void mma_tf32(float* d, const uint32_t* a, const uint32_t* b) {
    asm volatile(
        "mma.sync.aligned.m16n8k8.row.col.f32.tf32.tf32.f32 "
        "{%0,%1,%2,%3}, {%4,%5,%6,%7}, {%8,%9}, {%0,%1,%2,%3};\n"
        : "+f"(d[0]), "+f"(d[1]), "+f"(d[2]), "+f"(d[3])
        : "r"(a[0]), "r"(a[1]), "r"(a[2]), "r"(a[3]), "r"(b[0]), "r"(b[1]));
}

__global__ void __launch_bounds__(256)
tf32gemm_dual(const float* __restrict__ X,
              const float* __restrict__ W0, const float* __restrict__ W1,
              float* __restrict__ out0, float* __restrict__ out1,
              const float* __restrict__ bias, int relu,
              int M, int K, int HC) {
    __shared__ float As[2][16 * GPITCH];
    __shared__ float Bs[2][16 * GPITCH];

    const int t  = threadIdx.x;
    const int bm = blockIdx.y * 128;
    int bn = blockIdx.x * 128;

    const float* W = W0;
    float* out = out0;
    int col0 = bn;
    if (W1 != nullptr && bn >= HC) { W = W1; out = out1; col0 = bn - HC; }

    // global loaders
    const int arA = t >> 2;            // 0..63
    const int acA = t & 3;             // k-quad
    const float* Ap0 = X + (size_t)(bm + arA) * K + acA * 4;
    const float* Ap1 = X + (size_t)(bm + arA + 64) * K + acA * 4;
    const int bkB = t >> 5;            // 0..7
    const int bcB = t & 31;
    const float* Bp0 = W + (size_t)bkB * HC + col0 + bcB * 4;
    const float* Bp1 = Bp0 + (size_t)8 * HC;

    // warp/lane geometry
    const int warp = t >> 5;
    const int lane = t & 31;
    const int m0w = (warp >> 2) * 64;
    const int n0w = (warp & 3) * 32;
    const int tq   = lane & 3;
    const int trow = lane >> 2;

    float acc[4][4][4];
    #pragma unroll
    for (int i = 0; i < 4; i++)
        #pragma unroll
        for (int j = 0; j < 4; j++)
            #pragma unroll
            for (int r = 0; r < 4; r++) acc[i][j][r] = 0.f;

    float4 pa0, pa1, pb0, pb1;

    // prologue
    pa0 = *(const float4*)(Ap0);
    pa1 = *(const float4*)(Ap1);
    pb0 = *(const float4*)(Bp0);
    pb1 = *(const float4*)(Bp1);
    {
        float* As_ = As[0];
        float* Bs_ = Bs[0];
        As_[(acA * 4 + 0) * GPITCH + arA]      = pa0.x;
        As_[(acA * 4 + 1) * GPITCH + arA]      = pa0.y;
        As_[(acA * 4 + 2) * GPITCH + arA]      = pa0.z;
        As_[(acA * 4 + 3) * GPITCH + arA]      = pa0.w;
        As_[(acA * 4 + 0) * GPITCH + arA + 64] = pa1.x;
        As_[(acA * 4 + 1) * GPITCH + arA + 64] = pa1.y;
        As_[(acA * 4 + 2) * GPITCH + arA + 64] = pa1.z;
        As_[(acA * 4 + 3) * GPITCH + arA + 64] = pa1.w;
        *(float4*)&Bs_[bkB * GPITCH + bcB * 4]       = pb0;
        *(float4*)&Bs_[(bkB + 8) * GPITCH + bcB * 4] = pb1;
    }
    __syncthreads();

    const int nt = K >> 4;
    for (int it = 0; it < nt; it++) {
        if (it + 1 < nt) {
            int k0 = (it + 1) << 4;
            pa0 = *(const float4*)(Ap0 + k0);
            pa1 = *(const float4*)(Ap1 + k0);
            pb0 = *(const float4*)(Bp0 + (size_t)k0 * HC);
            pb1 = *(const float4*)(Bp1 + (size_t)k0 * HC);
        }
        const float* As_ = As[it & 1];
        const float* Bs_ = Bs[it & 1];

        #pragma unroll
        for (int ks = 0; ks < 16; ks += 8) {
            uint32_t aH[4][4], aL[4][4], bH[4][2], bL[4][2];
            #pragma unroll
            for (int i = 0; i < 4; i++) {
                int m = m0w + i * 16 + trow;
                float x0 = As_[(ks + tq) * GPITCH + m];
                float x1 = As_[(ks + tq) * GPITCH + m + 8];
                float x2 = As_[(ks + tq + 4) * GPITCH + m];
                float x3 = As_[(ks + tq + 4) * GPITCH + m + 8];
                tf32split(x0, aH[i][0], aL[i][0]);
                tf32split(x1, aH[i][1], aL[i][1]);
                tf32split(x2, aH[i][2], aL[i][2]);
                tf32split(x3, aH[i][3], aL[i][3]);
            }
            #pragma unroll
            for (int j = 0; j < 4; j++) {
                int n = n0w + j * 8 + trow;
                float y0 = Bs_[(ks + tq) * GPITCH + n];
                float y1 = Bs_[(ks + tq + 4) * GPITCH + n];
                tf32split(y0, bH[j][0], bL[j][0]);
                tf32split(y1, bH[j][1], bL[j][1]);
            }
            #pragma unroll
            for (int i = 0; i < 4; i++)
                #pragma unroll
                for (int j = 0; j < 4; j++) {
                    mma_tf32(acc[i][j], aH[i], bH[j]);
                    mma_tf32(acc[i][j], aH[i], bL[j]);
                    mma_tf32(acc[i][j], aL[i], bH[j]);
                }
        }

        if (it + 1 < nt) {
            __syncthreads();
            float* Aw = As[(it + 1) & 1];
            float* Bw = Bs[(it + 1) & 1];
            Aw[(acA * 4 + 0) * GPITCH + arA]      = pa0.x;
            Aw[(acA * 4 + 1) * GPITCH + arA]      = pa0.y;
            Aw[(acA * 4 + 2) * GPITCH + arA]      = pa0.z;
            Aw[(acA * 4 + 3) * GPITCH + arA]      = pa0.w;
            Aw[(acA * 4 + 0) * GPITCH + arA + 64] = pa1.x;
            Aw[(acA * 4 + 1) * GPITCH + arA + 64] = pa1.y;
            Aw[(acA * 4 + 2) * GPITCH + arA + 64] = pa1.z;
            Aw[(acA * 4 + 3) * GPITCH + arA + 64] = pa1.w;
            *(float4*)&Bw[bkB * GPITCH + bcB * 4]       = pb0;
            *(float4*)&Bw[(bkB + 8) * GPITCH + bcB * 4] = pb1;
            __syncthreads();
        }
    }

    // epilogue: acc[i][j] rows {trow, trow+8}, cols {2*tq, 2*tq+1}
    #pragma unroll
    for (int i = 0; i < 4; i++) {
        int gr0 = bm + m0w + i * 16 + trow;
        #pragma unroll
        for (int j = 0; j < 4; j++) {
            int gc = col0 + n0w + j * 8 + tq * 2;
            float2 v0 = make_float2(acc[i][j][0], acc[i][j][1]);
            float2 v1 = make_float2(acc[i][j][2], acc[i][j][3]);
            if (bias) {
                float b0 = bias[gc], b1 = bias[gc + 1];
                v0.x += b0; v0.y += b1;
                v1.x += b0; v1.y += b1;
            }
            if (relu) {
                v0.x = fmaxf(v0.x, 0.f); v0.y = fmaxf(v0.y, 0.f);
                v1.x = fmaxf(v1.x, 0.f); v1.y = fmaxf(v1.y, 0.f);
            }
            *(float2*)&out[(size_t)gr0 * HC + gc]       = v0;
            *(float2*)&out[(size_t)(gr0 + 8) * HC + gc] = v1;
        }
    }
}

// ---------------------------------------------------------------------------
// Edge logits
// ---------------------------------------------------------------------------
__global__ void edge_logit_kernel(const float4* __restrict__ xl4, const float4* __restrict__ xr4,
                                  const int* __restrict__ src, const int* __restrict__ dst,
                                  const float4* __restrict__ att4,
                                  float* __restrict__ logit,
                                  int E, int Nn, int C4, int c4shift, int HC4, int WPE) {
    int gw   = (blockIdx.x * blockDim.x + threadIdx.x) >> 5;
    int lane = threadIdx.x & 31;
    int Et   = E + Nn;
    if (gw >= Et * WPE) return;
    int e    = gw / WPE;
    int wsub = gw - e * WPE;
    int hperw = 32 >> c4shift;
    int hloc = lane >> c4shift;
    int h    = wsub * hperw + hloc;
    int j    = lane & (C4 - 1);

    int s, d;
    if (e < E) { s = src[e]; d = dst[e]; } else { s = d = e - E; }

    float4 l = xl4[(size_t)s * HC4 + h * C4 + j];
    float4 r = xr4[(size_t)d * HC4 + h * C4 + j];
    float4 a = att4[h * C4 + j];
    float v, acc = 0.f;
    v = l.x + r.x; v = (v > 0.f) ? v : 0.2f * v; acc += a.x * v;
    v = l.y + r.y; v = (v > 0.f) ? v : 0.2f * v; acc += a.y * v;
    v = l.z + r.z; v = (v > 0.f) ? v : 0.2f * v; acc += a.z * v;
    v = l.w + r.w; v = (v > 0.f) ? v : 0.2f * v; acc += a.w * v;

    for (int off = C4 >> 1; off > 0; off >>= 1)
        acc += __shfl_xor_sync(0xffffffffu, acc, off);
    if (j == 0)
        logit[e * HEADS + h] = acc;
}

// ---------------------------------------------------------------------------
// Per-node softmax (CSR) -> per-edge alpha
// ---------------------------------------------------------------------------
__global__ void node_softmax_kernel(const int* __restrict__ ptr, const int* __restrict__ eid,
                                    const float4* __restrict__ logit4,
                                    float4* __restrict__ alpha4, int Nn) {
    int n    = (blockIdx.x * blockDim.x + threadIdx.x) >> 5;
    int lane = threadIdx.x & 31;
    if (n >= Nn) return;
    int beg = ptr[n], end = ptr[n + 1];

    float m0 = -1e30f, m1 = -1e30f, m2 = -1e30f, m3 = -1e30f;
    for (int i = beg + lane; i < end; i += 32) {
        float4 lg = logit4[eid[i]];
        m0 = fmaxf(m0, lg.x); m1 = fmaxf(m1, lg.y);
        m2 = fmaxf(m2, lg.z); m3 = fmaxf(m3, lg.w);
    }
    #pragma unroll
    for (int off = 16; off > 0; off >>= 1) {
        m0 = fmaxf(m0, __shfl_xor_sync(0xffffffffu, m0, off));
        m1 = fmaxf(m1, __shfl_xor_sync(0xffffffffu, m1, off));
        m2 = fmaxf(m2, __shfl_xor_sync(0xffffffffu, m2, off));
        m3 = fmaxf(m3, __shfl_xor_sync(0xffffffffu, m3, off));
    }
    float z0 = 0.f, z1 = 0.f, z2 = 0.f, z3 = 0.f;
    for (int i = beg + lane; i < end; i += 32) {
        float4 lg = logit4[eid[i]];
        z0 += expf(lg.x - m0); z1 += expf(lg.y - m1);
        z2 += expf(lg.z - m2); z3 += expf(lg.w - m3);
    }
    #pragma unroll
    for (int off = 16; off > 0; off >>= 1) {
        z0 += __shfl_xor_sync(0xffffffffu, z0, off);
        z1 += __shfl_xor_sync(0xffffffffu, z1, off);
        z2 += __shfl_xor_sync(0xffffffffu, z2, off);
        z3 += __shfl_xor_sync(0xffffffffu, z3, off);
    }
    float i0 = 1.f / (z0 + 1e-16f), i1 = 1.f / (z1 + 1e-16f);
    float i2 = 1.f / (z2 + 1e-16f), i3 = 1.f / (z3 + 1e-16f);
    for (int i = beg + lane; i < end; i += 32) {
        int e = eid[i];
        float4 lg = logit4[e];
        float4 al;
        al.x = expf(lg.x - m0) * i0;
        al.y = expf(lg.y - m1) * i1;
        al.z = expf(lg.z - m2) * i2;
        al.w = expf(lg.w - m3) * i3;
        alpha4[e] = al;
    }
}

// ---------------------------------------------------------------------------
// Aggregation: warp per node, register accumulation
// ---------------------------------------------------------------------------
template <int NV4>
__global__ void node_agg_kernel(const float4* __restrict__ xl4, const int* __restrict__ src,
                                const int* __restrict__ ptr, const int* __restrict__ eid,
                                const float* __restrict__ alpha,
                                float4* __restrict__ out4,
                                int E, int Nn, int HC4, int c4shift) {
    int n    = (blockIdx.x * blockDim.x + threadIdx.x) >> 5;
    int lane = threadIdx.x & 31;
    if (n >= Nn) return;
    int beg = ptr[n], end = ptr[n + 1];

    float4 acc[NV4];
    #pragma unroll
    for (int r = 0; r < NV4; r++) acc[r] = make_float4(0.f, 0.f, 0.f, 0.f);

    for (int i = beg; i < end; i++) {
        int e = eid[i];
        int s = (e < E) ? src[e] : n;
        const float4* row = xl4 + (size_t)s * HC4;
        #pragma unroll
        for (int r = 0; r < NV4; r++) {
            int j = r * 32 + lane;
            float a = alpha[e * HEADS + (j >> c4shift)];
            float4 x = row[j];
            acc[r].x += a * x.x; acc[r].y += a * x.y;
            acc[r].z += a * x.z; acc[r].w += a * x.w;
        }
    }
    #pragma unroll
    for (int r = 0; r < NV4; r++)
        out4[(size_t)n * HC4 + r * 32 + lane] = acc[r];
}

// ---------------------------------------------------------------------------
// GraphNorm
// ---------------------------------------------------------------------------
__global__ void colstats_kernel(const float* __restrict__ x, float* __restrict__ stats,
                                int Nn, int Cn) {
    int r0   = blockIdx.x * 64;
    int rend = min(r0 + 64, Nn);
    float s[2] = {0.f, 0.f}, q[2] = {0.f, 0.f};
    for (int r = r0; r < rend; r++) {
        const float* row = x + (size_t)r * Cn;
        int k = 0;
        for (int c = threadIdx.x; c < Cn; c += 256, k++) {
            float v = row[c];
            s[k] += v; q[k] += v * v;
        }
    }
    int k = 0;
    for (int c = threadIdx.x; c < Cn; c += 256, k++) {
        atomicAdd(&stats[c],      s[k]);
        atomicAdd(&stats[Cn + c], q[k]);
    }
}

__global__ void colscale_kernel(const float* __restrict__ stats,
                                const float* __restrict__ bias,
                                const float* __restrict__ gw, const float* __restrict__ gb,
                                const float* __restrict__ gm,
                                float* __restrict__ colA, float* __restrict__ colS,
                                int Nn, int Cn) {
    int c = blockIdx.x * blockDim.x + threadIdx.x;
    if (c >= Cn) return;
    float invN = 1.0f / (float)Nn;
    float ma = stats[c] * invN;
    float q  = stats[Cn + c] * invN;
    float b  = bias[c];
    float mx = ma + b;
    float tt = b - gm[c] * mx;
    float var = q + 2.f * tt * ma + tt * tt;
    var = fmaxf(var, 0.f);
    float A = gw[c] * rsqrtf(var + 1e-5f);
    colA[c] = A;
    colS[c] = A * tt + gb[c];
}

__global__ void norm_relu_kernel(float4* __restrict__ x4,
                                 const float4* __restrict__ colA4,
                                 const float4* __restrict__ colS4,
                                 int total4, int Cn4) {
    int i = blockIdx.x * blockDim.x + threadIdx.x;
    if (i >= total4) return;
    int c = i % Cn4;
    float4 v = x4[i];
    float4 A = colA4[c];
    float4 S = colS4[c];
    v.x = fmaxf(A.x * v.x + S.x, 0.f);
    v.y = fmaxf(A.y * v.y + S.y, 0.f);
    v.z = fmaxf(A.z * v.z + S.z, 0.f);
    v.w = fmaxf(A.w * v.w + S.w, 0.f);
    x4[i] = v;
}

// ---------------------------------------------------------------------------
// Pooling
// ---------------------------------------------------------------------------
__global__ void gate_kernel(const float* __restrict__ hidden, const float* __restrict__ aW2,
                            const float* __restrict__ ab2, float* __restrict__ gate, int Nn) {
    int gw   = (blockIdx.x * blockDim.x + threadIdx.x) >> 5;
    int lane = threadIdx.x & 31;
    if (gw >= Nn) return;
    const float* hr = hidden + (size_t)gw * 128;
    float acc = 0.f;
    #pragma unroll
    for (int c = 0; c < 4; c++) acc += hr[lane + c * 32] * aW2[lane + c * 32];
    #pragma unroll
    for (int o = 16; o > 0; o >>= 1) acc += __shfl_down_sync(0xffffffffu, acc, o);
    if (lane == 0) gate[gw] = acc + ab2[0];
}

__global__ void graph_bounds_kernel(const int* __restrict__ batch,
                                    int* __restrict__ gs, int* __restrict__ ge, int Nn) {
    int n = blockIdx.x * blockDim.x + threadIdx.x;
    if (n >= Nn) return;
    int b = batch[n];
    atomicMin(&gs[b], n);
    atomicMax(&ge[b], n + 1);
}

__global__ void pool_kernel(const float* __restrict__ x, const float* __restrict__ gate,
                            const int* __restrict__ gs, const int* __restrict__ ge,
                            float* __restrict__ out) {
    __shared__ float red[128];
    __shared__ float wbuf[128];
    int b = blockIdx.x;
    int t = threadIdx.x;
    int beg = gs[b], end = ge[b];

    float mx = -1e30f;
    for (int n = beg + t; n < end; n += 128) mx = fmaxf(mx, gate[n]);
    red[t] = mx; __syncthreads();
    for (int o = 64; o > 0; o >>= 1) {
        if (t < o) red[t] = fmaxf(red[t], red[t + o]);
        __syncthreads();
    }
    float m = red[0];
    if (m < -1e29f) m = 0.f;
    __syncthreads();

    float zs = 0.f;
    for (int n = beg + t; n < end; n += 128) zs += expf(gate[n] - m);
    red[t] = zs; __syncthreads();
    for (int o = 64; o > 0; o >>= 1) {
        if (t < o) red[t] += red[t + o];
        __syncthreads();
    }
    float inv = 1.f / (red[0] + 1e-16f);
    __syncthreads();

    float acc = 0.f;
    for (int base = beg; base < end; base += 128) {
        int n = base + t;
        wbuf[t] = (n < end) ? expf(gate[n] - m) * inv : 0.f;
        __syncthreads();
        int cnt = min(128, end - base);
        for (int k = 0; k < cnt; k++)
            acc += wbuf[k] * x[(size_t)(base + k) * 128 + t];
        __syncthreads();
    }
    out[b * 128 + t] = acc;
}

// ---------------------------------------------------------------------------
// Host orchestration
// ---------------------------------------------------------------------------
extern "C" void kernel_launch(void* const* d_in, const int* in_sizes, int n_in,
                              void* d_out, int out_size) {
    const float* x0    = (const float*)d_in[0];
    const int*   ei    = (const int*)d_in[1];
    const int*   batch = (const int*)d_in[2];

    int N = in_sizes[0] / 960;
    int E = in_sizes[1] / 2;
    const int* src = ei;
    const int* dst = ei + E;
    int Et = E + N;

    float *p_xl, *p_xr, *p_a0, *p_a1, *p_logit, *p_alpha, *p_stats, *p_colA, *p_colS;
    float *p_hidden, *p_gate;
    int *p_deg, *p_ptr, *p_pos, *p_eid, *p_gs, *p_ge;
    cudaGetSymbolAddress((void**)&p_xl,    g_xl);
    cudaGetSymbolAddress((void**)&p_xr,    g_xr);
    cudaGetSymbolAddress((void**)&p_a0,    g_act0);
    cudaGetSymbolAddress((void**)&p_a1,    g_act1);
    cudaGetSymbolAddress((void**)&p_logit, g_logit);
    cudaGetSymbolAddress((void**)&p_alpha, g_alpha);
    cudaGetSymbolAddress((void**)&p_stats, g_stats);
    cudaGetSymbolAddress((void**)&p_colA,  g_colA);
    cudaGetSymbolAddress((void**)&p_colS,  g_colS);
    cudaGetSymbolAddress((void**)&p_hidden,g_hidden);
    cudaGetSymbolAddress((void**)&p_gate,  g_gate);
    cudaGetSymbolAddress((void**)&p_deg,   g_deg);
    cudaGetSymbolAddress((void**)&p_ptr,   g_ptr);
    cudaGetSymbolAddress((void**)&p_pos,   g_pos);
    cudaGetSymbolAddress((void**)&p_eid,   g_eid);
    cudaGetSymbolAddress((void**)&p_gs,    g_gs);
    cudaGetSymbolAddress((void**)&p_ge,    g_ge);

    // ---- CSR build ----
    fill_i_kernel<<<(N + 255) / 256, 256>>>(p_deg, 0, N);
    csr_count_kernel<<<(Et + 255) / 256, 256>>>(dst, p_deg, E, N);
    csr_scan_kernel<<<1, 1024>>>(p_deg, p_ptr, p_pos, N);
    csr_scatter_kernel<<<(Et + 255) / 256, 256>>>(dst, p_pos, p_eid, E, N);

    const int din[3] = {960, 512, 256};
    const int Cc[3]  = {128, 64, 32};

    const float* xin = x0;
    float* acts[2] = {p_a0, p_a1};

    for (int l = 0; l < 3; l++) {
        int K  = din[l];
        int C  = Cc[l];
        int HC = HEADS * C;
        int C4 = C / 4;
        int c4shift = (C == 128) ? 5 : (C == 64 ? 4 : 3);
        int HC4 = HC / 4;
        int WPE = (HEADS * C4) / 32;
        const float* Wl  = (const float*)d_in[3 + 7 * l];
        const float* Wr  = (const float*)d_in[4 + 7 * l];
        const float* att = (const float*)d_in[5 + 7 * l];
        const float* bb  = (const float*)d_in[6 + 7 * l];
        const float* gw  = (const float*)d_in[7 + 7 * l];
        const float* gb  = (const float*)d_in[8 + 7 * l];
        const float* gm  = (const float*)d_in[9 + 7 * l];
        float* out = acts[l & 1];

        // fused dual tensor-core GEMM -> xl, xr
        dim3 gblk(2 * HC / 128, N / 128);
        tf32gemm_dual<<<gblk, 256>>>(xin, Wl, Wr, p_xl, p_xr, nullptr, 0, N, K, HC);

        // edge logits
        int warps = Et * WPE;
        edge_logit_kernel<<<(warps * 32 + 255) / 256, 256>>>(
            (const float4*)p_xl, (const float4*)p_xr, src, dst,
            (const float4*)att, p_logit, E, N, C4, c4shift, HC4, WPE);

        // per-node softmax -> alpha
        node_softmax_kernel<<<(N * 32 + 255) / 256, 256>>>(
            p_ptr, p_eid, (const float4*)p_logit, (float4*)p_alpha, N);

        // aggregation
        int aggBlocks = (N * 32 + 255) / 256;
        if (HC4 == 128)
            node_agg_kernel<4><<<aggBlocks, 256>>>((const float4*)p_xl, src, p_ptr, p_eid,
                                                   p_alpha, (float4*)out, E, N, HC4, c4shift);
        else if (HC4 == 64)
            node_agg_kernel<2><<<aggBlocks, 256>>>((const float4*)p_xl, src, p_ptr, p_eid,
                                                   p_alpha, (float4*)out, E, N, HC4, c4shift);
        else
            node_agg_kernel<1><<<aggBlocks, 256>>>((const float4*)p_xl, src, p_ptr, p_eid,
                                                   p_alpha, (float4*)out, E, N, HC4, c4shift);

        // GraphNorm (bias folded) + ReLU
        fill_f_kernel<<<(2 * HC + 255) / 256, 256>>>(p_stats, 0.f, 2 * HC);
        colstats_kernel<<<(N + 63) / 64, 256>>>(out, p_stats, N, HC);
        colscale_kernel<<<(HC + 255) / 256, 256>>>(p_stats, bb, gw, gb, gm,
                                                   p_colA, p_colS, N, HC);
        norm_relu_kernel<<<(N * HC4 + 255) / 256, 256>>>(
            (float4*)out, (const float4*)p_colA, (const float4*)p_colS, N * HC4, HC4);

        xin = out;
    }

    // ---- Pooling ----
    const float* aW1 = (const float*)d_in[24];
    const float* ab1 = (const float*)d_in[25];
    const float* aW2 = (const float*)d_in[26];
    const float* ab2 = (const float*)d_in[27];

    dim3 hblk(1, N / 128);
    tf32gemm_dual<<<hblk, 256>>>(xin, aW1, nullptr, p_hidden, nullptr, ab1, 1, N, 128, 128);
    gate_kernel<<<(N * 32 + 255) / 256, 256>>>(p_hidden, aW2, ab2, p_gate, N);

    fill_i_kernel<<<1, NGRAPH>>>(p_gs, N, NGRAPH);
    fill_i_kernel<<<1, NGRAPH>>>(p_ge, 0, NGRAPH);
    graph_bounds_kernel<<<(N + 255) / 256, 256>>>(batch, p_gs, p_ge, N);
    pool_kernel<<<NGRAPH, 128>>>(xin, p_gate, p_gs, p_ge, (float*)d_out);
}

// round 4
// speedup vs baseline: 2.0566x; 1.1842x over previous
#include <cuda_runtime.h>
#include <cuda_bf16.h>
#include <math.h>
#include <stdint.h>

// ---------------------------------------------------------------------------
// Problem constants
// ---------------------------------------------------------------------------
#define NMAX   16000
#define EMAX   256000
#define ETMAX  (EMAX + NMAX)
#define HEADS  4
#define MAXHC  512
#define NGRAPH 64

// ---------------------------------------------------------------------------
// Static device scratch
// ---------------------------------------------------------------------------
__device__ float g_xl   [NMAX * MAXHC];
__device__ float g_xr   [NMAX * MAXHC];
__device__ float g_act0 [NMAX * MAXHC];
__device__ float g_act1 [NMAX * MAXHC];
__device__ float g_logit[ETMAX * HEADS];
__device__ float g_alpha[ETMAX * HEADS];
__device__ float g_stats[2 * MAXHC];
__device__ float g_colA [MAXHC];
__device__ float g_colS [MAXHC];
__device__ float g_hidden[NMAX * 128];
__device__ float g_gate [NMAX];
__device__ int   g_deg  [NMAX];
__device__ int   g_ptr  [NMAX + 1];
__device__ int   g_pos  [NMAX];
__device__ int   g_eid  [ETMAX];
__device__ int   g_gs   [NGRAPH];
__device__ int   g_ge   [NGRAPH];

// ---------------------------------------------------------------------------
// Small utility kernels
// ---------------------------------------------------------------------------
__global__ void fill_f_kernel(float* __restrict__ p, float v, int n) {
    int i = blockIdx.x * blockDim.x + threadIdx.x;
    if (i < n) p[i] = v;
}
__global__ void fill_i_kernel(int* __restrict__ p, int v, int n) {
    int i = blockIdx.x * blockDim.x + threadIdx.x;
    if (i < n) p[i] = v;
}

// ---------------------------------------------------------------------------
// CSR build over dst
// ---------------------------------------------------------------------------
__global__ void csr_count_kernel(const int* __restrict__ dst, int* __restrict__ deg,
                                 int E, int Nn) {
    int e = blockIdx.x * blockDim.x + threadIdx.x;
    int Et = E + Nn;
    if (e >= Et) return;
    int d = (e < E) ? dst[e] : (e - E);
    atomicAdd(&deg[d], 1);
}

__global__ void csr_scan_kernel(const int* __restrict__ deg, int* __restrict__ ptr,
                                int* __restrict__ pos, int n) {
    __shared__ int ss[1024];
    int t = threadIdx.x;
    int base = t * 16;
    int loc[16];
    int s = 0;
    #pragma unroll
    for (int i = 0; i < 16; i++) {
        int v = (base + i < n) ? deg[base + i] : 0;
        loc[i] = v; s += v;
    }
    ss[t] = s;
    __syncthreads();
    for (int off = 1; off < 1024; off <<= 1) {
        int v = (t >= off) ? ss[t - off] : 0;
        __syncthreads();
        ss[t] += v;
        __syncthreads();
    }
    int run = (t > 0) ? ss[t - 1] : 0;
    #pragma unroll
    for (int i = 0; i < 16; i++) {
        if (base + i < n) {
            ptr[base + i] = run;
            pos[base + i] = run;
            run += loc[i];
        }
    }
    if (t == 1023) ptr[n] = ss[1023];
}

__global__ void csr_scatter_kernel(const int* __restrict__ dst, int* __restrict__ pos,
                                   int* __restrict__ eid, int E, int Nn) {
    int e = blockIdx.x * blockDim.x + threadIdx.x;
    int Et = E + Nn;
    if (e >= Et) return;
    int d = (e < E) ? dst[e] : (e - E);
    int slot = atomicAdd(&pos[d], 1);
    eid[slot] = e;
}

// ---------------------------------------------------------------------------
// bf16 3-term tensor-core GEMM (error-compensated split, pre-split in SMEM).
// out[M,HC] = X[M,K] @ W[K,HC]; dual-weight option (Wl|Wr) via grid.x.
// Block 128x128xK16, 8 warps (2x4), warp tile 64x32, mma m16n8k16.bf16.
// Assumes M%128==0, K%16==0, HC%128==0.
//
// SMEM layout per array: [row 0..127][word 0..8] (pitch 9 words, 1 pad).
// Word s holds bf16 pair for k-pair p where s = 2*(p&3) + (p>>2), so a
// fragment's pair tq is at word 2*tq and pair tq+4 at word 2*tq+1.
// ---------------------------------------------------------------------------
#define BPITCH 9

__device__ __forceinline__ void packsplit(float x0, float x1,
                                          uint32_t& hi, uint32_t& lo) {
    __nv_bfloat16 h0 = __float2bfloat16_rn(x0);
    __nv_bfloat16 h1 = __float2bfloat16_rn(x1);
    float l0f = x0 - __bfloat162float(h0);
    float l1f = x1 - __bfloat162float(h1);
    __nv_bfloat16 l0 = __float2bfloat16_rn(l0f);
    __nv_bfloat16 l1 = __float2bfloat16_rn(l1f);
    __nv_bfloat162 hp = __halves2bfloat162(h0, h1);
    __nv_bfloat162 lp = __halves2bfloat162(l0, l1);
    hi = *reinterpret_cast<uint32_t*>(&hp);
    lo = *reinterpret_cast<uint32_t*>(&lp);
}

__device__ __forceinline__ void mma_bf16(float* d, const uint32_t* a, const uint32_t* b) {
    asm volatile(
        "mma.sync.aligned.m16n8k16.row.col.f32.bf16.bf16.f32 "
        "{%0,%1,%2,%3}, {%4,%5,%6,%7}, {%8,%9}, {%0,%1,%2,%3};\n"
        : "+f"(d[0]), "+f"(d[1]), "+f"(d[2]), "+f"(d[3])
        : "r"(a[0]), "r"(a[1]), "r"(a[2]), "r"(a[3]), "r"(b[0]), "r"(b[1]));
}

__global__ void __launch_bounds__(256)
bf16gemm_dual(const float* __restrict__ X,
              const float* __restrict__ W0, const float* __restrict__ W1,
              float* __restrict__ out0, float* __restrict__ out1,
              const float* __restrict__ bias, int relu,
              int M, int K, int HC) {
    __shared__ uint32_t AsH[2][128 * BPITCH];
    __shared__ uint32_t AsL[2][128 * BPITCH];
    __shared__ uint32_t BsH[2][128 * BPITCH];
    __shared__ uint32_t BsL[2][128 * BPITCH];

    const int t  = threadIdx.x;
    const int bm = blockIdx.y * 128;
    int bn = blockIdx.x * 128;

    const float* W = W0;
    float* out = out0;
    int col0 = bn;
    if (W1 != nullptr && bn >= HC) { W = W1; out = out1; col0 = bn - HC; }

    // A loader: thread -> (row ar, k-half ah); two float4 along k.
    const int ar = t >> 1;
    const int ah = t & 1;
    const float* Ap = X + (size_t)(bm + ar) * K + ah * 8;
    // B loader: warp w handles k-pair p=w; lane covers n = lane + 32j.
    const int wA = t >> 5;
    const int lane = t & 31;
    const float* Bp = W + (size_t)(2 * wA) * HC + col0 + lane;
    const int bs = 2 * (wA & 3) + (wA >> 2);

    // warp/lane geometry for mma
    const int m0w = (wA >> 2) * 64;
    const int n0w = (wA & 3) * 32;
    const int tq   = lane & 3;
    const int trow = lane >> 2;

    float acc[4][4][4];
    #pragma unroll
    for (int i = 0; i < 4; i++)
        #pragma unroll
        for (int j = 0; j < 4; j++)
            #pragma unroll
            for (int r = 0; r < 4; r++) acc[i][j][r] = 0.f;

    float4 fa0, fa1;
    float rb0[4], rb1[4];

    // prologue: tile 0
    fa0 = *(const float4*)(Ap);
    fa1 = *(const float4*)(Ap + 4);
    #pragma unroll
    for (int j = 0; j < 4; j++) {
        rb0[j] = Bp[32 * j];
        rb1[j] = Bp[(size_t)HC + 32 * j];
    }
    {
        uint32_t h, l;
        int ab = ar * BPITCH + ah;
        packsplit(fa0.x, fa0.y, h, l); AsH[0][ab + 0] = h; AsL[0][ab + 0] = l;
        packsplit(fa0.z, fa0.w, h, l); AsH[0][ab + 2] = h; AsL[0][ab + 2] = l;
        packsplit(fa1.x, fa1.y, h, l); AsH[0][ab + 4] = h; AsL[0][ab + 4] = l;
        packsplit(fa1.z, fa1.w, h, l); AsH[0][ab + 6] = h; AsL[0][ab + 6] = l;
        #pragma unroll
        for (int j = 0; j < 4; j++) {
            packsplit(rb0[j], rb1[j], h, l);
            int bb = (lane + 32 * j) * BPITCH + bs;
            BsH[0][bb] = h; BsL[0][bb] = l;
        }
    }
    __syncthreads();

    const int nt = K >> 4;
    for (int it = 0; it < nt; it++) {
        if (it + 1 < nt) {
            int k0 = (it + 1) << 4;
            fa0 = *(const float4*)(Ap + k0);
            fa1 = *(const float4*)(Ap + k0 + 4);
            #pragma unroll
            for (int j = 0; j < 4; j++) {
                rb0[j] = Bp[(size_t)k0 * HC + 32 * j];
                rb1[j] = Bp[(size_t)(k0 + 1) * HC + 32 * j];
            }
        }
        const uint32_t* AsH_ = AsH[it & 1];
        const uint32_t* AsL_ = AsL[it & 1];
        const uint32_t* BsH_ = BsH[it & 1];
        const uint32_t* BsL_ = BsL[it & 1];

        uint32_t aH[4][4], aL[4][4], bH[4][2], bL[4][2];
        #pragma unroll
        for (int i = 0; i < 4; i++) {
            int m = m0w + i * 16 + trow;
            int b0 = m * BPITCH + 2 * tq;
            int b1 = (m + 8) * BPITCH + 2 * tq;
            aH[i][0] = AsH_[b0]; aH[i][2] = AsH_[b0 + 1];
            aH[i][1] = AsH_[b1]; aH[i][3] = AsH_[b1 + 1];
            aL[i][0] = AsL_[b0]; aL[i][2] = AsL_[b0 + 1];
            aL[i][1] = AsL_[b1]; aL[i][3] = AsL_[b1 + 1];
        }
        #pragma unroll
        for (int j = 0; j < 4; j++) {
            int n = n0w + j * 8 + trow;
            int nb = n * BPITCH + 2 * tq;
            bH[j][0] = BsH_[nb]; bH[j][1] = BsH_[nb + 1];
            bL[j][0] = BsL_[nb]; bL[j][1] = BsL_[nb + 1];
        }
        #pragma unroll
        for (int i = 0; i < 4; i++)
            #pragma unroll
            for (int j = 0; j < 4; j++) {
                mma_bf16(acc[i][j], aH[i], bH[j]);
                mma_bf16(acc[i][j], aH[i], bL[j]);
                mma_bf16(acc[i][j], aL[i], bH[j]);
            }

        if (it + 1 < nt) {
            __syncthreads();
            uint32_t* AwH = AsH[(it + 1) & 1];
            uint32_t* AwL = AsL[(it + 1) & 1];
            uint32_t* BwH = BsH[(it + 1) & 1];
            uint32_t* BwL = BsL[(it + 1) & 1];
            uint32_t h, l;
            int ab = ar * BPITCH + ah;
            packsplit(fa0.x, fa0.y, h, l); AwH[ab + 0] = h; AwL[ab + 0] = l;
            packsplit(fa0.z, fa0.w, h, l); AwH[ab + 2] = h; AwL[ab + 2] = l;
            packsplit(fa1.x, fa1.y, h, l); AwH[ab + 4] = h; AwL[ab + 4] = l;
            packsplit(fa1.z, fa1.w, h, l); AwH[ab + 6] = h; AwL[ab + 6] = l;
            #pragma unroll
            for (int j = 0; j < 4; j++) {
                packsplit(rb0[j], rb1[j], h, l);
                int bb = (lane + 32 * j) * BPITCH + bs;
                BwH[bb] = h; BwL[bb] = l;
            }
            __syncthreads();
        }
    }

    // epilogue: acc[i][j]: rows {trow, trow+8}, cols {2tq, 2tq+1}
    #pragma unroll
    for (int i = 0; i < 4; i++) {
        int gr0 = bm + m0w + i * 16 + trow;
        #pragma unroll
        for (int j = 0; j < 4; j++) {
            int gc = col0 + n0w + j * 8 + tq * 2;
            float2 v0 = make_float2(acc[i][j][0], acc[i][j][1]);
            float2 v1 = make_float2(acc[i][j][2], acc[i][j][3]);
            if (bias) {
                float b0 = bias[gc], b1 = bias[gc + 1];
                v0.x += b0; v0.y += b1;
                v1.x += b0; v1.y += b1;
            }
            if (relu) {
                v0.x = fmaxf(v0.x, 0.f); v0.y = fmaxf(v0.y, 0.f);
                v1.x = fmaxf(v1.x, 0.f); v1.y = fmaxf(v1.y, 0.f);
            }
            *(float2*)&out[(size_t)gr0 * HC + gc]       = v0;
            *(float2*)&out[(size_t)(gr0 + 8) * HC + gc] = v1;
        }
    }
}

// ---------------------------------------------------------------------------
// Edge logits
// ---------------------------------------------------------------------------
__global__ void edge_logit_kernel(const float4* __restrict__ xl4, const float4* __restrict__ xr4,
                                  const int* __restrict__ src, const int* __restrict__ dst,
                                  const float4* __restrict__ att4,
                                  float* __restrict__ logit,
                                  int E, int Nn, int C4, int c4shift, int HC4, int WPE) {
    int gw   = (blockIdx.x * blockDim.x + threadIdx.x) >> 5;
    int lane = threadIdx.x & 31;
    int Et   = E + Nn;
    if (gw >= Et * WPE) return;
    int e    = gw / WPE;
    int wsub = gw - e * WPE;
    int hperw = 32 >> c4shift;
    int hloc = lane >> c4shift;
    int h    = wsub * hperw + hloc;
    int j    = lane & (C4 - 1);

    int s, d;
    if (e < E) { s = src[e]; d = dst[e]; } else { s = d = e - E; }

    float4 l = xl4[(size_t)s * HC4 + h * C4 + j];
    float4 r = xr4[(size_t)d * HC4 + h * C4 + j];
    float4 a = att4[h * C4 + j];
    float v, acc = 0.f;
    v = l.x + r.x; v = (v > 0.f) ? v : 0.2f * v; acc += a.x * v;
    v = l.y + r.y; v = (v > 0.f) ? v : 0.2f * v; acc += a.y * v;
    v = l.z + r.z; v = (v > 0.f) ? v : 0.2f * v; acc += a.z * v;
    v = l.w + r.w; v = (v > 0.f) ? v : 0.2f * v; acc += a.w * v;

    for (int off = C4 >> 1; off > 0; off >>= 1)
        acc += __shfl_xor_sync(0xffffffffu, acc, off);
    if (j == 0)
        logit[e * HEADS + h] = acc;
}

// ---------------------------------------------------------------------------
// Per-node softmax (CSR) -> per-edge alpha
// ---------------------------------------------------------------------------
__global__ void node_softmax_kernel(const int* __restrict__ ptr, const int* __restrict__ eid,
                                    const float4* __restrict__ logit4,
                                    float4* __restrict__ alpha4, int Nn) {
    int n    = (blockIdx.x * blockDim.x + threadIdx.x) >> 5;
    int lane = threadIdx.x & 31;
    if (n >= Nn) return;
    int beg = ptr[n], end = ptr[n + 1];

    float m0 = -1e30f, m1 = -1e30f, m2 = -1e30f, m3 = -1e30f;
    for (int i = beg + lane; i < end; i += 32) {
        float4 lg = logit4[eid[i]];
        m0 = fmaxf(m0, lg.x); m1 = fmaxf(m1, lg.y);
        m2 = fmaxf(m2, lg.z); m3 = fmaxf(m3, lg.w);
    }
    #pragma unroll
    for (int off = 16; off > 0; off >>= 1) {
        m0 = fmaxf(m0, __shfl_xor_sync(0xffffffffu, m0, off));
        m1 = fmaxf(m1, __shfl_xor_sync(0xffffffffu, m1, off));
        m2 = fmaxf(m2, __shfl_xor_sync(0xffffffffu, m2, off));
        m3 = fmaxf(m3, __shfl_xor_sync(0xffffffffu, m3, off));
    }
    float z0 = 0.f, z1 = 0.f, z2 = 0.f, z3 = 0.f;
    for (int i = beg + lane; i < end; i += 32) {
        float4 lg = logit4[eid[i]];
        z0 += expf(lg.x - m0); z1 += expf(lg.y - m1);
        z2 += expf(lg.z - m2); z3 += expf(lg.w - m3);
    }
    #pragma unroll
    for (int off = 16; off > 0; off >>= 1) {
        z0 += __shfl_xor_sync(0xffffffffu, z0, off);
        z1 += __shfl_xor_sync(0xffffffffu, z1, off);
        z2 += __shfl_xor_sync(0xffffffffu, z2, off);
        z3 += __shfl_xor_sync(0xffffffffu, z3, off);
    }
    float i0 = 1.f / (z0 + 1e-16f), i1 = 1.f / (z1 + 1e-16f);
    float i2 = 1.f / (z2 + 1e-16f), i3 = 1.f / (z3 + 1e-16f);
    for (int i = beg + lane; i < end; i += 32) {
        int e = eid[i];
        float4 lg = logit4[e];
        float4 al;
        al.x = expf(lg.x - m0) * i0;
        al.y = expf(lg.y - m1) * i1;
        al.z = expf(lg.z - m2) * i2;
        al.w = expf(lg.w - m3) * i3;
        alpha4[e] = al;
    }
}

// ---------------------------------------------------------------------------
// Aggregation: warp per node, register accumulation
// ---------------------------------------------------------------------------
template <int NV4>
__global__ void node_agg_kernel(const float4* __restrict__ xl4, const int* __restrict__ src,
                                const int* __restrict__ ptr, const int* __restrict__ eid,
                                const float* __restrict__ alpha,
                                float4* __restrict__ out4,
                                int E, int Nn, int HC4, int c4shift) {
    int n    = (blockIdx.x * blockDim.x + threadIdx.x) >> 5;
    int lane = threadIdx.x & 31;
    if (n >= Nn) return;
    int beg = ptr[n], end = ptr[n + 1];

    float4 acc[NV4];
    #pragma unroll
    for (int r = 0; r < NV4; r++) acc[r] = make_float4(0.f, 0.f, 0.f, 0.f);

    for (int i = beg; i < end; i++) {
        int e = eid[i];
        int s = (e < E) ? src[e] : n;
        const float4* row = xl4 + (size_t)s * HC4;
        #pragma unroll
        for (int r = 0; r < NV4; r++) {
            int j = r * 32 + lane;
            float a = alpha[e * HEADS + (j >> c4shift)];
            float4 x = row[j];
            acc[r].x += a * x.x; acc[r].y += a * x.y;
            acc[r].z += a * x.z; acc[r].w += a * x.w;
        }
    }
    #pragma unroll
    for (int r = 0; r < NV4; r++)
        out4[(size_t)n * HC4 + r * 32 + lane] = acc[r];
}

// ---------------------------------------------------------------------------
// GraphNorm
// ---------------------------------------------------------------------------
__global__ void colstats_kernel(const float* __restrict__ x, float* __restrict__ stats,
                                int Nn, int Cn) {
    int r0   = blockIdx.x * 64;
    int rend = min(r0 + 64, Nn);
    float s[2] = {0.f, 0.f}, q[2] = {0.f, 0.f};
    for (int r = r0; r < rend; r++) {
        const float* row = x + (size_t)r * Cn;
        int k = 0;
        for (int c = threadIdx.x; c < Cn; c += 256, k++) {
            float v = row[c];
            s[k] += v; q[k] += v * v;
        }
    }
    int k = 0;
    for (int c = threadIdx.x; c < Cn; c += 256, k++) {
        atomicAdd(&stats[c],      s[k]);
        atomicAdd(&stats[Cn + c], q[k]);
    }
}

__global__ void colscale_kernel(const float* __restrict__ stats,
                                const float* __restrict__ bias,
                                const float* __restrict__ gw, const float* __restrict__ gb,
                                const float* __restrict__ gm,
                                float* __restrict__ colA, float* __restrict__ colS,
                                int Nn, int Cn) {
    int c = blockIdx.x * blockDim.x + threadIdx.x;
    if (c >= Cn) return;
    float invN = 1.0f / (float)Nn;
    float ma = stats[c] * invN;
    float q  = stats[Cn + c] * invN;
    float b  = bias[c];
    float mx = ma + b;
    float tt = b - gm[c] * mx;
    float var = q + 2.f * tt * ma + tt * tt;
    var = fmaxf(var, 0.f);
    float A = gw[c] * rsqrtf(var + 1e-5f);
    colA[c] = A;
    colS[c] = A * tt + gb[c];
}

__global__ void norm_relu_kernel(float4* __restrict__ x4,
                                 const float4* __restrict__ colA4,
                                 const float4* __restrict__ colS4,
                                 int total4, int Cn4) {
    int i = blockIdx.x * blockDim.x + threadIdx.x;
    if (i >= total4) return;
    int c = i % Cn4;
    float4 v = x4[i];
    float4 A = colA4[c];
    float4 S = colS4[c];
    v.x = fmaxf(A.x * v.x + S.x, 0.f);
    v.y = fmaxf(A.y * v.y + S.y, 0.f);
    v.z = fmaxf(A.z * v.z + S.z, 0.f);
    v.w = fmaxf(A.w * v.w + S.w, 0.f);
    x4[i] = v;
}

// ---------------------------------------------------------------------------
// Pooling
// ---------------------------------------------------------------------------
__global__ void gate_kernel(const float* __restrict__ hidden, const float* __restrict__ aW2,
                            const float* __restrict__ ab2, float* __restrict__ gate, int Nn) {
    int gw   = (blockIdx.x * blockDim.x + threadIdx.x) >> 5;
    int lane = threadIdx.x & 31;
    if (gw >= Nn) return;
    const float* hr = hidden + (size_t)gw * 128;
    float acc = 0.f;
    #pragma unroll
    for (int c = 0; c < 4; c++) acc += hr[lane + c * 32] * aW2[lane + c * 32];
    #pragma unroll
    for (int o = 16; o > 0; o >>= 1) acc += __shfl_down_sync(0xffffffffu, acc, o);
    if (lane == 0) gate[gw] = acc + ab2[0];
}

__global__ void graph_bounds_kernel(const int* __restrict__ batch,
                                    int* __restrict__ gs, int* __restrict__ ge, int Nn) {
    int n = blockIdx.x * blockDim.x + threadIdx.x;
    if (n >= Nn) return;
    int b = batch[n];
    atomicMin(&gs[b], n);
    atomicMax(&ge[b], n + 1);
}

__global__ void pool_kernel(const float* __restrict__ x, const float* __restrict__ gate,
                            const int* __restrict__ gs, const int* __restrict__ ge,
                            float* __restrict__ out) {
    __shared__ float red[128];
    __shared__ float wbuf[128];
    int b = blockIdx.x;
    int t = threadIdx.x;
    int beg = gs[b], end = ge[b];

    float mx = -1e30f;
    for (int n = beg + t; n < end; n += 128) mx = fmaxf(mx, gate[n]);
    red[t] = mx; __syncthreads();
    for (int o = 64; o > 0; o >>= 1) {
        if (t < o) red[t] = fmaxf(red[t], red[t + o]);
        __syncthreads();
    }
    float m = red[0];
    if (m < -1e29f) m = 0.f;
    __syncthreads();

    float zs = 0.f;
    for (int n = beg + t; n < end; n += 128) zs += expf(gate[n] - m);
    red[t] = zs; __syncthreads();
    for (int o = 64; o > 0; o >>= 1) {
        if (t < o) red[t] += red[t + o];
        __syncthreads();
    }
    float inv = 1.f / (red[0] + 1e-16f);
    __syncthreads();

    float acc = 0.f;
    for (int base = beg; base < end; base += 128) {
        int n = base + t;
        wbuf[t] = (n < end) ? expf(gate[n] - m) * inv : 0.f;
        __syncthreads();
        int cnt = min(128, end - base);
        for (int k = 0; k < cnt; k++)
            acc += wbuf[k] * x[(size_t)(base + k) * 128 + t];
        __syncthreads();
    }
    out[b * 128 + t] = acc;
}

// ---------------------------------------------------------------------------
// Host orchestration
// ---------------------------------------------------------------------------
extern "C" void kernel_launch(void* const* d_in, const int* in_sizes, int n_in,
                              void* d_out, int out_size) {
    const float* x0    = (const float*)d_in[0];
    const int*   ei    = (const int*)d_in[1];
    const int*   batch = (const int*)d_in[2];

    int N = in_sizes[0] / 960;
    int E = in_sizes[1] / 2;
    const int* src = ei;
    const int* dst = ei + E;
    int Et = E + N;

    float *p_xl, *p_xr, *p_a0, *p_a1, *p_logit, *p_alpha, *p_stats, *p_colA, *p_colS;
    float *p_hidden, *p_gate;
    int *p_deg, *p_ptr, *p_pos, *p_eid, *p_gs, *p_ge;
    cudaGetSymbolAddress((void**)&p_xl,    g_xl);
    cudaGetSymbolAddress((void**)&p_xr,    g_xr);
    cudaGetSymbolAddress((void**)&p_a0,    g_act0);
    cudaGetSymbolAddress((void**)&p_a1,    g_act1);
    cudaGetSymbolAddress((void**)&p_logit, g_logit);
    cudaGetSymbolAddress((void**)&p_alpha, g_alpha);
    cudaGetSymbolAddress((void**)&p_stats, g_stats);
    cudaGetSymbolAddress((void**)&p_colA,  g_colA);
    cudaGetSymbolAddress((void**)&p_colS,  g_colS);
    cudaGetSymbolAddress((void**)&p_hidden,g_hidden);
    cudaGetSymbolAddress((void**)&p_gate,  g_gate);
    cudaGetSymbolAddress((void**)&p_deg,   g_deg);
    cudaGetSymbolAddress((void**)&p_ptr,   g_ptr);
    cudaGetSymbolAddress((void**)&p_pos,   g_pos);
    cudaGetSymbolAddress((void**)&p_eid,   g_eid);
    cudaGetSymbolAddress((void**)&p_gs,    g_gs);
    cudaGetSymbolAddress((void**)&p_ge,    g_ge);

    // ---- CSR build ----
    fill_i_kernel<<<(N + 255) / 256, 256>>>(p_deg, 0, N);
    csr_count_kernel<<<(Et + 255) / 256, 256>>>(dst, p_deg, E, N);
    csr_scan_kernel<<<1, 1024>>>(p_deg, p_ptr, p_pos, N);
    csr_scatter_kernel<<<(Et + 255) / 256, 256>>>(dst, p_pos, p_eid, E, N);

    const int din[3] = {960, 512, 256};
    const int Cc[3]  = {128, 64, 32};

    const float* xin = x0;
    float* acts[2] = {p_a0, p_a1};

    for (int l = 0; l < 3; l++) {
        int K  = din[l];
        int C  = Cc[l];
        int HC = HEADS * C;
        int C4 = C / 4;
        int c4shift = (C == 128) ? 5 : (C == 64 ? 4 : 3);
        int HC4 = HC / 4;
        int WPE = (HEADS * C4) / 32;
        const float* Wl  = (const float*)d_in[3 + 7 * l];
        const float* Wr  = (const float*)d_in[4 + 7 * l];
        const float* att = (const float*)d_in[5 + 7 * l];
        const float* bb  = (const float*)d_in[6 + 7 * l];
        const float* gw  = (const float*)d_in[7 + 7 * l];
        const float* gb  = (const float*)d_in[8 + 7 * l];
        const float* gm  = (const float*)d_in[9 + 7 * l];
        float* out = acts[l & 1];

        // fused dual tensor-core GEMM -> xl, xr
        dim3 gblk(2 * HC / 128, N / 128);
        bf16gemm_dual<<<gblk, 256>>>(xin, Wl, Wr, p_xl, p_xr, nullptr, 0, N, K, HC);

        // edge logits
        int warps = Et * WPE;
        edge_logit_kernel<<<(warps * 32 + 255) / 256, 256>>>(
            (const float4*)p_xl, (const float4*)p_xr, src, dst,
            (const float4*)att, p_logit, E, N, C4, c4shift, HC4, WPE);

        // per-node softmax -> alpha
        node_softmax_kernel<<<(N * 32 + 255) / 256, 256>>>(
            p_ptr, p_eid, (const float4*)p_logit, (float4*)p_alpha, N);

        // aggregation
        int aggBlocks = (N * 32 + 255) / 256;
        if (HC4 == 128)
            node_agg_kernel<4><<<aggBlocks, 256>>>((const float4*)p_xl, src, p_ptr, p_eid,
                                                   p_alpha, (float4*)out, E, N, HC4, c4shift);
        else if (HC4 == 64)
            node_agg_kernel<2><<<aggBlocks, 256>>>((const float4*)p_xl, src, p_ptr, p_eid,
                                                   p_alpha, (float4*)out, E, N, HC4, c4shift);
        else
            node_agg_kernel<1><<<aggBlocks, 256>>>((const float4*)p_xl, src, p_ptr, p_eid,
                                                   p_alpha, (float4*)out, E, N, HC4, c4shift);

        // GraphNorm (bias folded) + ReLU
        fill_f_kernel<<<(2 * HC + 255) / 256, 256>>>(p_stats, 0.f, 2 * HC);
        colstats_kernel<<<(N + 63) / 64, 256>>>(out, p_stats, N, HC);
        colscale_kernel<<<(HC + 255) / 256, 256>>>(p_stats, bb, gw, gb, gm,
                                                   p_colA, p_colS, N, HC);
        norm_relu_kernel<<<(N * HC4 + 255) / 256, 256>>>(
            (float4*)out, (const float4*)p_colA, (const float4*)p_colS, N * HC4, HC4);

        xin = out;
    }

    // ---- Pooling ----
    const float* aW1 = (const float*)d_in[24];
    const float* ab1 = (const float*)d_in[25];
    const float* aW2 = (const float*)d_in[26];
    const float* ab2 = (const float*)d_in[27];

    dim3 hblk(1, N / 128);
    bf16gemm_dual<<<hblk, 256>>>(xin, aW1, nullptr, p_hidden, nullptr, ab1, 1, N, 128, 128);
    gate_kernel<<<(N * 32 + 255) / 256, 256>>>(p_hidden, aW2, ab2, p_gate, N);

    fill_i_kernel<<<1, NGRAPH>>>(p_gs, N, NGRAPH);
    fill_i_kernel<<<1, NGRAPH>>>(p_ge, 0, NGRAPH);
    graph_bounds_kernel<<<(N + 255) / 256, 256>>>(batch, p_gs, p_ge, N);
    pool_kernel<<<NGRAPH, 128>>>(xin, p_gate, p_gs, p_ge, (float*)d_out);
}